// round 15
// baseline (speedup 1.0000x reference)
#include <cuda_runtime.h>
#include <cuda_bf16.h>
#include <cstdint>
#include <math.h>

// ---------------------------------------------------------------------------
// Bidirectional 3-layer ConvLSTM encoder.
// L1/L2 serial h-conv on tensor cores (packed uint4 weight fragments),
// L1 x-conv via FUSED implicit-im2col mma.sync GEMM,
// L2 x-conv via pipelined mma.sync GEMM, L3 scalar persistent.
// B=8, T=24. L1: 48x56 Cin=6 F=32. L2: 24x28 Cin=64 F=32. L3: 12x14 Cin=64 F=12.
// ---------------------------------------------------------------------------

#define BB 8
#define TT 24

// ---- scratch (__device__ globals) ----
__device__ __align__(16) float g_seq1[(size_t)BB * TT * 48 * 56 * 64];
__device__ __align__(16) float g_p1  [(size_t)BB * TT * 24 * 28 * 64];
__device__ __align__(16) float g_seq2[(size_t)BB * TT * 24 * 28 * 64];
__device__ __align__(16) float g_p2  [(size_t)BB * TT * 12 * 14 * 64];
__device__ __align__(16) float g_zbase[(size_t)2 * BB * TT * 48 * 56 * 128];
__device__ __align__(16) float g_c   [(size_t)2 * BB * 48 * 56 * 32];
// L2 xconv GEMM operands
__device__ __align__(16) __nv_bfloat16 g_Ahi[(size_t)129024 * 576];
__device__ __align__(16) __nv_bfloat16 g_Alo[(size_t)129024 * 576];
__device__ __align__(16) __nv_bfloat16 g_Bhi[2 * 128 * 576];
__device__ __align__(16) __nv_bfloat16 g_Blo[2 * 128 * 576];
// L1 xconv weights (K padded 54 -> 64)
__device__ __align__(16) __nv_bfloat16 g_B1hi[2 * 128 * 64];
__device__ __align__(16) __nv_bfloat16 g_B1lo[2 * 128 * 64];
// h state as bf16 hi/lo, double-buffered (max size = L1)
__device__ __align__(16) __nv_bfloat16 g_hhiA[(size_t)2 * BB * 2688 * 32];
__device__ __align__(16) __nv_bfloat16 g_hloA[(size_t)2 * BB * 2688 * 32];
__device__ __align__(16) __nv_bfloat16 g_hhiB[(size_t)2 * BB * 2688 * 32];
__device__ __align__(16) __nv_bfloat16 g_hloB[(size_t)2 * BB * 2688 * 32];
// packed B-fragment tables: rec[(dir,tap,kc,nb8)][lane] = {bh0,bh1,bl0,bl1}
__device__ __align__(16) uint4 g_W1f4[2 * 9 * 2 * 16 * 32];
__device__ __align__(16) uint4 g_W2f4[2 * 9 * 2 * 16 * 32];

// ---------------------------------------------------------------------------
// mma.sync m16n8k16 bf16 (baseline PTX; conventions validated R9/R10).
// ---------------------------------------------------------------------------
__device__ __forceinline__ void mma_bf16(float c[4], const uint32_t a[4],
                                         const uint32_t b[2]) {
    asm volatile(
        "mma.sync.aligned.m16n8k16.row.col.f32.bf16.bf16.f32 "
        "{%0,%1,%2,%3}, {%4,%5,%6,%7}, {%8,%9}, {%0,%1,%2,%3};"
        : "+f"(c[0]), "+f"(c[1]), "+f"(c[2]), "+f"(c[3])
        : "r"(a[0]), "r"(a[1]), "r"(a[2]), "r"(a[3]), "r"(b[0]), "r"(b[1]));
}

// ---------------------------------------------------------------------------
// Prep: pack recurrent weights Wh[3,3,32,128] into per-lane uint4 fragment
// records (one LDG.128 per mma B-fragment).
// ---------------------------------------------------------------------------
__device__ __forceinline__ uint32_t pack_hi_pair(const float* src, int tap,
                                                 int kk, int oc) {
    const float w0 = src[(size_t)(tap * 32 + 2 * kk) * 128 + oc];
    const float w1 = src[(size_t)(tap * 32 + 2 * kk + 1) * 128 + oc];
    const __nv_bfloat16 h0 = __float2bfloat16_rn(w0);
    const __nv_bfloat16 h1 = __float2bfloat16_rn(w1);
    return (uint32_t)__bfloat16_as_ushort(h0) |
           ((uint32_t)__bfloat16_as_ushort(h1) << 16);
}
__device__ __forceinline__ uint32_t pack_lo_pair(const float* src, int tap,
                                                 int kk, int oc) {
    const float w0 = src[(size_t)(tap * 32 + 2 * kk) * 128 + oc];
    const float w1 = src[(size_t)(tap * 32 + 2 * kk + 1) * 128 + oc];
    const __nv_bfloat16 h0 = __float2bfloat16_rn(w0);
    const __nv_bfloat16 h1 = __float2bfloat16_rn(w1);
    const __nv_bfloat16 l0 = __float2bfloat16_rn(w0 - __bfloat162float(h0));
    const __nv_bfloat16 l1 = __float2bfloat16_rn(w1 - __bfloat162float(h1));
    return (uint32_t)__bfloat16_as_ushort(l0) |
           ((uint32_t)__bfloat16_as_ushort(l1) << 16);
}

__global__ void wfrag_kernel(const float* __restrict__ w1f,
                             const float* __restrict__ w1b,
                             const float* __restrict__ w2f,
                             const float* __restrict__ w2b) {
    int i = blockIdx.x * 256 + threadIdx.x;
    if (i >= 2 * 2 * 9 * 2 * 16 * 32) return;
    const int lane = i & 31;
    int r = i >> 5;
    const int nb8 = r & 15;
    r >>= 4;
    const int kc = r & 1;
    r >>= 1;
    const int tap = r % 9;
    r /= 9;
    const int dir = r & 1;
    const int layer = r >> 1;
    const float* src = layer ? (dir ? w2b : w2f) : (dir ? w1b : w1f);
    const int g = lane >> 2, t4 = lane & 3;
    const int oc = nb8 * 8 + g;
    const int kkA = kc * 8 + t4, kkB = kkA + 4;
    uint4 v;
    v.x = pack_hi_pair(src, tap, kkA, oc);
    v.y = pack_hi_pair(src, tap, kkB, oc);
    v.z = pack_lo_pair(src, tap, kkA, oc);
    v.w = pack_lo_pair(src, tap, kkB, oc);
    const size_t rec =
        ((((size_t)dir * 9 + tap) * 2 + kc) * 16 + nb8) * 32 + lane;
    (layer ? g_W2f4 : g_W1f4)[rec] = v;
}

// ---------------------------------------------------------------------------
// Serial h-conv step on tensor cores, fused gates (R13 design, unchanged).
// ---------------------------------------------------------------------------
template <int H, int W, int RPT, int XW, int XSH>
__global__ __launch_bounds__(256) void hconv_mma(
    const float* __restrict__ zbase,
    const __nv_bfloat16* __restrict__ hhi, const __nv_bfloat16* __restrict__ hlo,
    __nv_bfloat16* __restrict__ hhi_o, __nv_bfloat16* __restrict__ hlo_o,
    float* __restrict__ cstate,
    const uint4* __restrict__ Wf4,
    float* __restrict__ seq, int seqC, int j) {
    constexpr int HW = H * W;
    constexpr int SXW = XW + 2;
    constexpr int SPIX = (RPT + 2) * SXW;
    constexpr int PSW = 20;
    constexpr int ZS = 129;
    constexpr int A_BYTES = SPIX * PSW * 4 * 2;
    constexpr int Z_BYTES = RPT * XW * ZS * 4;
    constexpr int SBYTES = (A_BYTES > Z_BYTES) ? A_BYTES : Z_BYTES;
    __shared__ __align__(16) char smraw[SBYTES];
    uint32_t* sHh = (uint32_t*)smraw;
    uint32_t* sHl = sHh + SPIX * PSW;
    float* sZ = (float*)smraw;

    const int tid = threadIdx.x;
    const int dir = blockIdx.z, b = blockIdx.y;
    const int dirb = dir * BB + b;
    const int y0 = blockIdx.x * RPT;
    const int t = dir ? (TT - 1 - j) : j;

    const __nv_bfloat16* hhib = hhi + (size_t)dirb * HW * 32;
    const __nv_bfloat16* hlob = hlo + (size_t)dirb * HW * 32;
    for (int idx = tid; idx < SPIX * 16; idx += 256) {
        const int pix = idx >> 4, cw = idx & 15;
        const int sry = pix / SXW, sx = pix - sry * SXW;
        const int y = y0 + sry - 1, imx = sx - 1;
        uint32_t vh = 0, vl = 0;
        if (y >= 0 && y < H && imx >= 0 && imx < W) {
            const size_t o = ((size_t)(y * W + imx)) * 32 + cw * 2;
            vh = *(const uint32_t*)(hhib + o);
            vl = *(const uint32_t*)(hlob + o);
        }
        sHh[pix * PSW + cw] = vh;
        sHl[pix * PSW + cw] = vl;
    }
    __syncthreads();

    const int lane = tid & 31, wid = tid >> 5;
    const int warp_m = wid & 1, warp_n = wid >> 1;
    const int g = lane >> 2, t4 = lane & 3;

    float acc[2][4][4];
#pragma unroll
    for (int mb = 0; mb < 2; mb++)
#pragma unroll
        for (int nb = 0; nb < 4; nb++)
#pragma unroll
            for (int q = 0; q < 4; q++) acc[mb][nb][q] = 0.f;

    const uint4* Wd = Wf4 + (size_t)dir * 9 * 2 * 16 * 32;

    for (int tap = 0; tap < 9; tap++) {
        const int dy = tap / 3, dx = tap % 3;
#pragma unroll
        for (int kc = 0; kc < 2; kc++) {
            uint4 wv[4];
            {
                const uint4* base =
                    Wd + ((size_t)(tap * 2 + kc) * 16 + warp_n * 4) * 32 + lane;
#pragma unroll
                for (int nb = 0; nb < 4; nb++) wv[nb] = base[nb * 32];
            }
            uint32_t ah[2][4], al[2][4];
#pragma unroll
            for (int mb = 0; mb < 2; mb++) {
                const int r = warp_m * 32 + mb * 16 + g;
                const int r2 = r + 8;
                const int sp0 = ((r >> XSH) + dy) * SXW + (r & (XW - 1)) + dx;
                const int sp1 = ((r2 >> XSH) + dy) * SXW + (r2 & (XW - 1)) + dx;
                const int kw = kc * 8 + t4;
                ah[mb][0] = sHh[sp0 * PSW + kw];
                ah[mb][1] = sHh[sp1 * PSW + kw];
                ah[mb][2] = sHh[sp0 * PSW + kw + 4];
                ah[mb][3] = sHh[sp1 * PSW + kw + 4];
                al[mb][0] = sHl[sp0 * PSW + kw];
                al[mb][1] = sHl[sp1 * PSW + kw];
                al[mb][2] = sHl[sp0 * PSW + kw + 4];
                al[mb][3] = sHl[sp1 * PSW + kw + 4];
            }
#pragma unroll
            for (int nb = 0; nb < 4; nb++) {
                uint32_t bh[2] = {wv[nb].x, wv[nb].y};
                uint32_t bl[2] = {wv[nb].z, wv[nb].w};
#pragma unroll
                for (int mb = 0; mb < 2; mb++) {
                    mma_bf16(acc[mb][nb], ah[mb], bh);
                    mma_bf16(acc[mb][nb], ah[mb], bl);
                    mma_bf16(acc[mb][nb], al[mb], bh);
                }
            }
        }
    }

    __syncthreads();
#pragma unroll
    for (int mb = 0; mb < 2; mb++) {
        const int r = warp_m * 32 + mb * 16 + g;
#pragma unroll
        for (int nb = 0; nb < 4; nb++) {
            const int col = warp_n * 32 + nb * 8 + t4 * 2;
            sZ[r * ZS + col] = acc[mb][nb][0];
            sZ[r * ZS + col + 1] = acc[mb][nb][1];
            sZ[(r + 8) * ZS + col] = acc[mb][nb][2];
            sZ[(r + 8) * ZS + col + 1] = acc[mb][nb][3];
        }
    }
    __syncthreads();

    const float* zb = zbase + ((size_t)dirb * TT + t) * HW * 128;
    float* cb = cstate + (size_t)dirb * HW * 32;
    __nv_bfloat16* hho = hhi_o + (size_t)dirb * HW * 32;
    __nv_bfloat16* hlo_ob = hlo_o + (size_t)dirb * HW * 32;
    float* sq = seq + ((size_t)(b * TT + t)) * HW * seqC + dir * 32;
#pragma unroll
    for (int it = 0; it < (RPT * XW * 32) / 256; it++) {
        const int item = tid + it * 256;
        const int f = item & 31;
        const int m = item >> 5;
        const int x = m & (XW - 1);
        if (x >= W) continue;
        const int pf = (y0 + (m >> XSH)) * W + x;
        const float zi = sZ[m * ZS + f] + zb[(size_t)pf * 128 + f];
        const float zf2 = sZ[m * ZS + 32 + f] + zb[(size_t)pf * 128 + 32 + f];
        const float zg = sZ[m * ZS + 64 + f] + zb[(size_t)pf * 128 + 64 + f];
        const float zo = sZ[m * ZS + 96 + f] + zb[(size_t)pf * 128 + 96 + f];
        const float ig = fmaxf(zi, 0.f);
        const float fg = fmaxf(zf2, 0.f);
        const float gg = tanhf(zg);
        const float og = fmaxf(zo, 0.f);
        const float cn = fg * cb[(size_t)pf * 32 + f] + ig * gg;
        const float hn = og * tanhf(cn);
        cb[(size_t)pf * 32 + f] = cn;
        const __nv_bfloat16 hh = __float2bfloat16_rn(hn);
        hho[(size_t)pf * 32 + f] = hh;
        hlo_ob[(size_t)pf * 32 + f] =
            __float2bfloat16_rn(hn - __bfloat162float(hh));
        sq[(size_t)pf * seqC + f] = hn;
    }
}

// ---------------------------------------------------------------------------
// L1 xconv weight split (K=54 padded to 64, k = tap*6+c ordering).
// ---------------------------------------------------------------------------
__global__ void bsplit1_kernel(const float* __restrict__ wf,
                               const float* __restrict__ wb) {
    const int i = blockIdx.x * blockDim.x + threadIdx.x;
    if (i >= 2 * 128 * 64) return;
    const int dir = i / (128 * 64);
    const int r = i % (128 * 64);
    const int n = r / 64, k = r % 64;
    float v = 0.f;
    if (k < 54) {
        const float* w = dir ? wb : wf;
        v = w[(size_t)k * 128 + n];
    }
    const __nv_bfloat16 hi = __float2bfloat16_rn(v);
    g_B1hi[i] = hi;
    g_B1lo[i] = __float2bfloat16_rn(v - __bfloat162float(hi));
}

// ---------------------------------------------------------------------------
// L1 x-conv GEMM with FUSED implicit im2col (no A materialization).
//   zbase_dir[M=516096, 128] = im2col(x)[M,54] x B1_dir[128,54]^T + bias
// grid = (4032, 2), block = 256 (8 warps: 4 M x 2 N). K padded to 64 (4 chunks).
// ---------------------------------------------------------------------------
__global__ __launch_bounds__(256) void gemm_xconv1(
    const float* __restrict__ xin,
    const __nv_bfloat16* __restrict__ B1hi, const __nv_bfloat16* __restrict__ B1lo,
    const float* __restrict__ bias_f, const float* __restrict__ bias_b,
    float* __restrict__ zbase) {
    constexpr int RS = 24;
    __shared__ __align__(16) __nv_bfloat16 sAh[128 * RS];
    __shared__ __align__(16) __nv_bfloat16 sAl[128 * RS];
    __shared__ __align__(16) __nv_bfloat16 sBh[128 * RS];
    __shared__ __align__(16) __nv_bfloat16 sBl[128 * RS];

    const int tid = threadIdx.x;
    const int lane = tid & 31, wid = tid >> 5;
    const int warp_m = wid & 3, warp_n = wid >> 2;
    const int g = lane >> 2, t4 = lane & 3;
    const int tile = blockIdx.x, dir = blockIdx.y;
    const size_t m0 = (size_t)tile * 128;

    const __nv_bfloat16* Bh = B1hi + (size_t)dir * 128 * 64;
    const __nv_bfloat16* Bl = B1lo + (size_t)dir * 128 * 64;
    const float* bias = dir ? bias_b : bias_f;

    float c[2][8][4];
#pragma unroll
    for (int mb = 0; mb < 2; mb++)
#pragma unroll
        for (int nb = 0; nb < 8; nb++)
#pragma unroll
            for (int q = 0; q < 4; q++) c[mb][nb][q] = 0.f;

    const int srow = tid & 127;
    const int shalf = tid >> 7;
    const int sdst = srow * RS + shalf * 8;

    // decode this thread's pixel once
    const int m = (int)m0 + srow;
    const int bt = m / 2688;
    const int pos = m - bt * 2688;
    const int py = pos / 56, px = pos - (pos / 56) * 56;
    const float* xb = xin + (size_t)bt * 2688 * 6;

    for (int kc = 0; kc < 4; kc++) {
        __syncthreads();
        // ---- stage A: fused im2col (8 elems), bf16 hi/lo ----
        {
            __nv_bfloat16 hi8[8], lo8[8];
            const int k0 = kc * 16 + shalf * 8;
#pragma unroll
            for (int q = 0; q < 8; q++) {
                const int k = k0 + q;
                float v = 0.f;
                if (k < 54) {
                    const int tap = k / 6, cc = k - 6 * tap;
                    const int yy = py + tap / 3 - 1;
                    const int xx = px + (tap % 3) - 1;
                    if (yy >= 0 && yy < 48 && xx >= 0 && xx < 56)
                        v = xb[(size_t)(yy * 56 + xx) * 6 + cc];
                }
                hi8[q] = __float2bfloat16_rn(v);
                lo8[q] = __float2bfloat16_rn(v - __bfloat162float(hi8[q]));
            }
            *(uint4*)(sAh + sdst) = *(const uint4*)hi8;
            *(uint4*)(sAl + sdst) = *(const uint4*)lo8;
        }
        // ---- stage B ----
        {
            const int ks = kc * 16 + shalf * 8;
            *(uint4*)(sBh + sdst) = *(const uint4*)(Bh + (size_t)srow * 64 + ks);
            *(uint4*)(sBl + sdst) = *(const uint4*)(Bl + (size_t)srow * 64 + ks);
        }
        __syncthreads();

        uint32_t ah[2][4], al[2][4];
#pragma unroll
        for (int mb = 0; mb < 2; mb++) {
            const int r0 = warp_m * 32 + mb * 16 + g;
            ah[mb][0] = *(const uint32_t*)(sAh + r0 * RS + t4 * 2);
            ah[mb][1] = *(const uint32_t*)(sAh + (r0 + 8) * RS + t4 * 2);
            ah[mb][2] = *(const uint32_t*)(sAh + r0 * RS + 8 + t4 * 2);
            ah[mb][3] = *(const uint32_t*)(sAh + (r0 + 8) * RS + 8 + t4 * 2);
            al[mb][0] = *(const uint32_t*)(sAl + r0 * RS + t4 * 2);
            al[mb][1] = *(const uint32_t*)(sAl + (r0 + 8) * RS + t4 * 2);
            al[mb][2] = *(const uint32_t*)(sAl + r0 * RS + 8 + t4 * 2);
            al[mb][3] = *(const uint32_t*)(sAl + (r0 + 8) * RS + 8 + t4 * 2);
        }
#pragma unroll
        for (int nb = 0; nb < 8; nb++) {
            const int n0 = warp_n * 64 + nb * 8 + g;
            uint32_t bh[2], bl[2];
            bh[0] = *(const uint32_t*)(sBh + n0 * RS + t4 * 2);
            bh[1] = *(const uint32_t*)(sBh + n0 * RS + 8 + t4 * 2);
            bl[0] = *(const uint32_t*)(sBl + n0 * RS + t4 * 2);
            bl[1] = *(const uint32_t*)(sBl + n0 * RS + 8 + t4 * 2);
#pragma unroll
            for (int mb = 0; mb < 2; mb++) {
                mma_bf16(c[mb][nb], ah[mb], bh);
                mma_bf16(c[mb][nb], ah[mb], bl);
                mma_bf16(c[mb][nb], al[mb], bh);
            }
        }
    }

    float* zd = zbase + ((size_t)dir * 516096 + m0) * 128;
#pragma unroll
    for (int mb = 0; mb < 2; mb++) {
        const int r0 = warp_m * 32 + mb * 16 + g;
#pragma unroll
        for (int nb = 0; nb < 8; nb++) {
            const int col = warp_n * 64 + nb * 8 + t4 * 2;
            zd[(size_t)r0 * 128 + col] = c[mb][nb][0] + bias[col];
            zd[(size_t)r0 * 128 + col + 1] = c[mb][nb][1] + bias[col + 1];
            zd[(size_t)(r0 + 8) * 128 + col] = c[mb][nb][2] + bias[col];
            zd[(size_t)(r0 + 8) * 128 + col + 1] = c[mb][nb][3] + bias[col + 1];
        }
    }
}

// ---------------------------------------------------------------------------
// L2 GEMM prep: im2col (uint4 granularity) + weight split.
// ---------------------------------------------------------------------------
__global__ void im2col2_kernel(const float* __restrict__ p1,
                               __nv_bfloat16* __restrict__ Ahi,
                               __nv_bfloat16* __restrict__ Alo) {
    const size_t idx = (size_t)blockIdx.x * 256 + threadIdx.x;
    if (idx >= (size_t)129024 * 72) return;
    const int k8 = (int)(idx % 72);
    const size_t m = idx / 72;
    const int k0 = k8 * 8;
    const int tap = k0 >> 6, c0 = k0 & 63;
    const int pos = (int)(m % 672);
    const size_t bt = m / 672;
    const int y = pos / 28, x = pos % 28;
    const int yy = y + tap / 3 - 1, xx = x + tap % 3 - 1;
    __nv_bfloat16 hi[8], lo[8];
    if (yy >= 0 && yy < 24 && xx >= 0 && xx < 28) {
        const float* src = p1 + ((bt * 24 + yy) * 28 + xx) * 64 + c0;
#pragma unroll
        for (int q = 0; q < 8; q++) {
            const float v = src[q];
            hi[q] = __float2bfloat16_rn(v);
            lo[q] = __float2bfloat16_rn(v - __bfloat162float(hi[q]));
        }
    } else {
#pragma unroll
        for (int q = 0; q < 8; q++) {
            hi[q] = __float2bfloat16_rn(0.f);
            lo[q] = hi[q];
        }
    }
    *(uint4*)(Ahi + m * 576 + k0) = *(const uint4*)hi;
    *(uint4*)(Alo + m * 576 + k0) = *(const uint4*)lo;
}

__global__ void bsplit2_kernel(const float* __restrict__ wf,
                               const float* __restrict__ wb,
                               __nv_bfloat16* __restrict__ Bhi,
                               __nv_bfloat16* __restrict__ Blo) {
    const int i = blockIdx.x * blockDim.x + threadIdx.x;
    if (i >= 2 * 128 * 576) return;
    const int dir = i / (128 * 576);
    const int r = i % (128 * 576);
    const int n = r / 576, k = r % 576;
    const float* w = dir ? wb : wf;
    const float v = w[(size_t)k * 128 + n];
    const __nv_bfloat16 hi = __float2bfloat16_rn(v);
    Bhi[i] = hi;
    Blo[i] = __float2bfloat16_rn(v - __bfloat162float(hi));
}

// ---------------------------------------------------------------------------
// L2 x-conv GEMM (mma.sync, register-prefetch pipelined). K = 576.
// ---------------------------------------------------------------------------
__global__ __launch_bounds__(256) void gemm_xconv2(
    const __nv_bfloat16* __restrict__ Ahi, const __nv_bfloat16* __restrict__ Alo,
    const __nv_bfloat16* __restrict__ Bhi, const __nv_bfloat16* __restrict__ Blo,
    const float* __restrict__ bias_f, const float* __restrict__ bias_b,
    float* __restrict__ zbase) {
    constexpr int RS = 24;
    __shared__ __align__(16) __nv_bfloat16 sAh[128 * RS];
    __shared__ __align__(16) __nv_bfloat16 sAl[128 * RS];
    __shared__ __align__(16) __nv_bfloat16 sBh[128 * RS];
    __shared__ __align__(16) __nv_bfloat16 sBl[128 * RS];

    const int tid = threadIdx.x;
    const int lane = tid & 31, wid = tid >> 5;
    const int warp_m = wid & 3, warp_n = wid >> 2;
    const int g = lane >> 2, t4 = lane & 3;
    const int tile = blockIdx.x, dir = blockIdx.y;
    const size_t m0 = (size_t)tile * 128;

    const __nv_bfloat16* Bh = Bhi + (size_t)dir * 128 * 576;
    const __nv_bfloat16* Bl = Blo + (size_t)dir * 128 * 576;
    const float* bias = dir ? bias_b : bias_f;

    float c[2][8][4];
#pragma unroll
    for (int mb = 0; mb < 2; mb++)
#pragma unroll
        for (int nb = 0; nb < 8; nb++)
#pragma unroll
            for (int q = 0; q < 4; q++) c[mb][nb][q] = 0.f;

    const int srow = tid & 127;
    const int shalf = tid >> 7;
    const int sdst = srow * RS + shalf * 8;

    uint4 pAh, pAl, pBh, pBl;
    {
        const size_t ks = shalf * 8;
        pAh = *(const uint4*)(Ahi + (m0 + srow) * 576 + ks);
        pAl = *(const uint4*)(Alo + (m0 + srow) * 576 + ks);
        pBh = *(const uint4*)(Bh + (size_t)srow * 576 + ks);
        pBl = *(const uint4*)(Bl + (size_t)srow * 576 + ks);
    }

    for (int kc = 0; kc < 36; kc++) {
        __syncthreads();
        *(uint4*)(sAh + sdst) = pAh;
        *(uint4*)(sAl + sdst) = pAl;
        *(uint4*)(sBh + sdst) = pBh;
        *(uint4*)(sBl + sdst) = pBl;
        __syncthreads();
        if (kc + 1 < 36) {
            const size_t ks = (size_t)(kc + 1) * 16 + shalf * 8;
            pAh = *(const uint4*)(Ahi + (m0 + srow) * 576 + ks);
            pAl = *(const uint4*)(Alo + (m0 + srow) * 576 + ks);
            pBh = *(const uint4*)(Bh + (size_t)srow * 576 + ks);
            pBl = *(const uint4*)(Bl + (size_t)srow * 576 + ks);
        }

        uint32_t ah[2][4], al[2][4];
#pragma unroll
        for (int mb = 0; mb < 2; mb++) {
            const int r0 = warp_m * 32 + mb * 16 + g;
            ah[mb][0] = *(const uint32_t*)(sAh + r0 * RS + t4 * 2);
            ah[mb][1] = *(const uint32_t*)(sAh + (r0 + 8) * RS + t4 * 2);
            ah[mb][2] = *(const uint32_t*)(sAh + r0 * RS + 8 + t4 * 2);
            ah[mb][3] = *(const uint32_t*)(sAh + (r0 + 8) * RS + 8 + t4 * 2);
            al[mb][0] = *(const uint32_t*)(sAl + r0 * RS + t4 * 2);
            al[mb][1] = *(const uint32_t*)(sAl + (r0 + 8) * RS + t4 * 2);
            al[mb][2] = *(const uint32_t*)(sAl + r0 * RS + 8 + t4 * 2);
            al[mb][3] = *(const uint32_t*)(sAl + (r0 + 8) * RS + 8 + t4 * 2);
        }
#pragma unroll
        for (int nb = 0; nb < 8; nb++) {
            const int n0 = warp_n * 64 + nb * 8 + g;
            uint32_t bh[2], bl[2];
            bh[0] = *(const uint32_t*)(sBh + n0 * RS + t4 * 2);
            bh[1] = *(const uint32_t*)(sBh + n0 * RS + 8 + t4 * 2);
            bl[0] = *(const uint32_t*)(sBl + n0 * RS + t4 * 2);
            bl[1] = *(const uint32_t*)(sBl + n0 * RS + 8 + t4 * 2);
#pragma unroll
            for (int mb = 0; mb < 2; mb++) {
                mma_bf16(c[mb][nb], ah[mb], bh);
                mma_bf16(c[mb][nb], ah[mb], bl);
                mma_bf16(c[mb][nb], al[mb], bh);
            }
        }
    }

    float* zd = zbase + ((size_t)dir * 129024 + m0) * 128;
#pragma unroll
    for (int mb = 0; mb < 2; mb++) {
        const int r0 = warp_m * 32 + mb * 16 + g;
#pragma unroll
        for (int nb = 0; nb < 8; nb++) {
            const int col = warp_n * 64 + nb * 8 + t4 * 2;
            zd[(size_t)r0 * 128 + col] = c[mb][nb][0] + bias[col];
            zd[(size_t)r0 * 128 + col + 1] = c[mb][nb][1] + bias[col + 1];
            zd[(size_t)(r0 + 8) * 128 + col] = c[mb][nb][2] + bias[col];
            zd[(size_t)(r0 + 8) * 128 + col + 1] = c[mb][nb][3] + bias[col + 1];
        }
    }
}

// ---------------------------------------------------------------------------
// Scalar x-conv over ALL timesteps (L3 only).
// ---------------------------------------------------------------------------
template <int CIN, int F, int H, int W, int TH, int SUBS>
__global__ __launch_bounds__(SUBS * 4 * F) void xconv_all(
    const float* __restrict__ xin,
    const float* __restrict__ wxf, const float* __restrict__ wxb,
    const float* __restrict__ bf, const float* __restrict__ bb,
    float* __restrict__ zbase) {
    constexpr int OC = 4 * F;
    constexpr int NT = SUBS * OC;
    constexpr int THS = TH / SUBS;
    constexpr int TW = 14, TW2 = 16;
    constexpr int CSTRIDE = (TH + 2) * TW2 + 4;
    constexpr int TILES_W = W / TW;

    __shared__ __align__(16) float smem[CIN * CSTRIDE];

    const int dir = blockIdx.z;
    const int bt = blockIdx.y;
    const int tile = blockIdx.x;
    const int ty0 = (tile / TILES_W) * TH;
    const int tx0 = (tile % TILES_W) * TW;

    const float* wx = dir ? wxb : wxf;
    const float* bi = dir ? bb : bf;
    const float* xb = xin + (size_t)bt * H * W * CIN;
    const int b = bt / TT, t = bt % TT;

    const int tid = threadIdx.x;

    constexpr int TOTAL = (TH + 2) * TW2 * CIN;
    for (int idx = tid; idx < TOTAL; idx += NT) {
        int c = idx % CIN;
        int p = idx / CIN;
        int yy = p / TW2, xx = p % TW2;
        int gy = ty0 + yy - 1, gx = tx0 + xx - 1;
        float v = 0.f;
        if (gy >= 0 && gy < H && gx >= 0 && gx < W)
            v = xb[((size_t)gy * W + gx) * CIN + c];
        smem[c * CSTRIDE + yy * TW2 + xx] = v;
    }
    __syncthreads();

    const int oc = tid % OC;
    const int sub = tid / OC;

    float acc[THS][TW];
    {
        const float bv = bi[oc];
#pragma unroll
        for (int y = 0; y < THS; y++)
#pragma unroll
            for (int p = 0; p < TW; p++) acc[y][p] = bv;
    }

#pragma unroll 2
    for (int c = 0; c < CIN; c++) {
        const float* sc = smem + c * CSTRIDE + sub * THS * TW2;
        float w[9];
#pragma unroll
        for (int k = 0; k < 9; k++) w[k] = wx[((size_t)k * CIN + c) * OC + oc];
#pragma unroll
        for (int iy = 0; iy < THS + 2; iy++) {
            float seg[TW2];
#pragma unroll
            for (int q = 0; q < TW2 / 4; q++) {
                const float4 v =
                    *reinterpret_cast<const float4*>(sc + iy * TW2 + 4 * q);
                seg[4 * q] = v.x; seg[4 * q + 1] = v.y;
                seg[4 * q + 2] = v.z; seg[4 * q + 3] = v.w;
            }
#pragma unroll
            for (int dy = 0; dy < 3; dy++) {
                const int ry = iy - dy;
                if (ry >= 0 && ry < THS) {
#pragma unroll
                    for (int dx = 0; dx < 3; dx++) {
                        const float ww = w[dy * 3 + dx];
#pragma unroll
                        for (int p = 0; p < TW; p++)
                            acc[ry][p] = fmaf(ww, seg[p + dx], acc[ry][p]);
                    }
                }
            }
        }
    }

    float* zb = zbase + (((size_t)(dir * BB + b) * TT + t) * H * W +
                         (size_t)ty0 * W + tx0) * OC;
#pragma unroll
    for (int y = 0; y < THS; y++)
#pragma unroll
        for (int p = 0; p < TW; p++)
            zb[((size_t)(sub * THS + y) * W + p) * OC + oc] = acc[y][p];
}

// ---------------------------------------------------------------------------
// Layer 3 persistent kernel.
// ---------------------------------------------------------------------------
__global__ __launch_bounds__(288) void lstm3_persistent(
    const float* __restrict__ zbase,
    const float* __restrict__ whf, const float* __restrict__ whb,
    float* __restrict__ out) {
    constexpr int F = 12, OC = 48, H = 12, W = 14, HW = H * W;
    constexpr int TW2 = 16, CSTR = (H + 2) * TW2 + 4;

    __shared__ __align__(16) float sh[F * CSTR];
    __shared__ __align__(16) float sz[HW * OC];

    const int dirb = blockIdx.x;
    const int dir = dirb / BB;
    const int b = dirb % BB;
    const float* wh = dir ? whb : whf;
    const int tid = threadIdx.x;

    for (int i = tid; i < F * CSTR; i += 288) sh[i] = 0.f;

    const int f = tid % F;
    const int pidx = tid / F;
    float creg[7];
#pragma unroll
    for (int k = 0; k < 7; k++) creg[k] = 0.f;

    const int oc = tid % OC;
    const int sub = tid / OC;

    for (int j = 0; j < TT; j++) {
        const int t = dir ? (TT - 1 - j) : j;
        __syncthreads();

        const float* zb = zbase + ((size_t)dirb * TT + t) * HW * OC;
        float acc[2][14];
#pragma unroll
        for (int y = 0; y < 2; y++)
#pragma unroll
            for (int p = 0; p < 14; p++)
                acc[y][p] = zb[((sub * 2 + y) * W + p) * OC + oc];

#pragma unroll
        for (int c = 0; c < F; c++) {
            const float* sc = sh + c * CSTR + sub * 2 * TW2;
            float w[9];
#pragma unroll
            for (int k = 0; k < 9; k++) w[k] = wh[((size_t)k * F + c) * OC + oc];
#pragma unroll
            for (int iy = 0; iy < 4; iy++) {
                float seg[16];
#pragma unroll
                for (int q = 0; q < 4; q++) {
                    const float4 v =
                        *reinterpret_cast<const float4*>(sc + iy * TW2 + 4 * q);
                    seg[4 * q] = v.x; seg[4 * q + 1] = v.y;
                    seg[4 * q + 2] = v.z; seg[4 * q + 3] = v.w;
                }
#pragma unroll
                for (int dy = 0; dy < 3; dy++) {
                    const int ry = iy - dy;
                    if (ry >= 0 && ry < 2) {
#pragma unroll
                        for (int dx = 0; dx < 3; dx++) {
                            const float ww = w[dy * 3 + dx];
#pragma unroll
                            for (int p = 0; p < 14; p++)
                                acc[ry][p] = fmaf(ww, seg[p + dx], acc[ry][p]);
                        }
                    }
                }
            }
        }

        __syncthreads();
#pragma unroll
        for (int y = 0; y < 2; y++)
#pragma unroll
            for (int p = 0; p < 14; p++)
                sz[((sub * 2 + y) * W + p) * OC + oc] = acc[y][p];
        __syncthreads();

        float* sq = out + ((size_t)(b * TT + t) * HW) * 24 + dir * F;
#pragma unroll
        for (int k = 0; k < 7; k++) {
            const int pos = pidx + 24 * k;
            const float zi = sz[pos * OC + f];
            const float zf = sz[pos * OC + F + f];
            const float zg = sz[pos * OC + 2 * F + f];
            const float zo = sz[pos * OC + 3 * F + f];
            const float ig = fmaxf(zi, 0.f);
            const float fg = fmaxf(zf, 0.f);
            const float gg = tanhf(zg);
            const float og = fmaxf(zo, 0.f);
            const float cn = fg * creg[k] + ig * gg;
            const float hn = og * tanhf(cn);
            creg[k] = cn;
            sq[pos * 24 + f] = hn;
            const int y = pos / W, x = pos % W;
            sh[f * CSTR + (y + 1) * TW2 + (x + 1)] = hn;
        }
    }

    __syncthreads();
    const size_t SEQ3 = (size_t)BB * TT * HW * 24;
    const size_t ST3 = (size_t)BB * HW * F;
    float* oh = out + SEQ3 + (size_t)(2 * dir) * ST3;
    float* ocst = out + SEQ3 + (size_t)(2 * dir + 1) * ST3;
#pragma unroll
    for (int k = 0; k < 7; k++) {
        const int pos = pidx + 24 * k;
        const int y = pos / W, x = pos % W;
        oh[((size_t)b * HW + pos) * F + f] = sh[f * CSTR + (y + 1) * TW2 + (x + 1)];
        ocst[((size_t)b * HW + pos) * F + f] = creg[k];
    }
}

// ---------------------------------------------------------------------------
// BN (eps=1e-3) then 2x2 max pool.
// ---------------------------------------------------------------------------
__global__ void bnpool_kernel(const float* __restrict__ in,
                              float* __restrict__ out,
                              const float* __restrict__ gg,
                              const float* __restrict__ bb,
                              const float* __restrict__ mm,
                              const float* __restrict__ vv, int H, int W,
                              int C) {
    const int HO = H / 2, WO = W / 2;
    const size_t total = (size_t)BB * TT * HO * WO * C;
    size_t i = (size_t)blockIdx.x * blockDim.x + threadIdx.x;
    if (i >= total) return;
    const int c = i % C;
    size_t r = i / C;
    const int x = r % WO;
    r /= WO;
    const int y = r % HO;
    r /= HO;
    const int t = r % TT;
    const int b = r / TT;

    const float scale = gg[c] * rsqrtf(vv[c] + 1e-3f);
    const float shift = bb[c] - mm[c] * scale;

    const float* base = in + ((size_t)(b * TT + t)) * H * W * C;
    float mx = -3.402823e38f;
#pragma unroll
    for (int dy = 0; dy < 2; dy++)
#pragma unroll
        for (int dx = 0; dx < 2; dx++) {
            float v =
                base[((size_t)(2 * y + dy) * W + (2 * x + dx)) * C + c] * scale +
                shift;
            mx = fmaxf(mx, v);
        }
    out[i] = mx;
}

// ---------------------------------------------------------------------------
// Host side
// ---------------------------------------------------------------------------
static float* sym_addr(const void* symbol) {
    void* p = nullptr;
    cudaGetSymbolAddress(&p, symbol);
    return (float*)p;
}
static __nv_bfloat16* sym_addr_bf(const void* symbol) {
    void* p = nullptr;
    cudaGetSymbolAddress(&p, symbol);
    return (__nv_bfloat16*)p;
}
static uint4* sym_addr_u4(const void* symbol) {
    void* p = nullptr;
    cudaGetSymbolAddress(&p, symbol);
    return (uint4*)p;
}

extern "C" void kernel_launch(void* const* d_in, const int* in_sizes, int n_in,
                              void* d_out, int out_size) {
    const float* x = (const float*)d_in[0];
    const float* w1f_x = (const float*)d_in[1];
    const float* w1f_h = (const float*)d_in[2];
    const float* b1f = (const float*)d_in[3];
    const float* w1b_x = (const float*)d_in[4];
    const float* w1b_h = (const float*)d_in[5];
    const float* b1b = (const float*)d_in[6];
    const float* w2f_x = (const float*)d_in[7];
    const float* w2f_h = (const float*)d_in[8];
    const float* b2f = (const float*)d_in[9];
    const float* w2b_x = (const float*)d_in[10];
    const float* w2b_h = (const float*)d_in[11];
    const float* b2b = (const float*)d_in[12];
    const float* w3f_x = (const float*)d_in[13];
    const float* w3f_h = (const float*)d_in[14];
    const float* b3f = (const float*)d_in[15];
    const float* w3b_x = (const float*)d_in[16];
    const float* w3b_h = (const float*)d_in[17];
    const float* b3b = (const float*)d_in[18];
    const float* bn1_g = (const float*)d_in[19];
    const float* bn1_b = (const float*)d_in[20];
    const float* bn1_m = (const float*)d_in[21];
    const float* bn1_v = (const float*)d_in[22];
    const float* bn2_g = (const float*)d_in[23];
    const float* bn2_b = (const float*)d_in[24];
    const float* bn2_m = (const float*)d_in[25];
    const float* bn2_v = (const float*)d_in[26];

    float* seq1 = sym_addr(g_seq1);
    float* p1 = sym_addr(g_p1);
    float* seq2 = sym_addr(g_seq2);
    float* p2 = sym_addr(g_p2);
    float* zb = sym_addr(g_zbase);
    float* cp = sym_addr(g_c);
    __nv_bfloat16* Ahi = sym_addr_bf(g_Ahi);
    __nv_bfloat16* Alo = sym_addr_bf(g_Alo);
    __nv_bfloat16* Bhi = sym_addr_bf(g_Bhi);
    __nv_bfloat16* Blo = sym_addr_bf(g_Blo);
    __nv_bfloat16* B1hi = sym_addr_bf(g_B1hi);
    __nv_bfloat16* B1lo = sym_addr_bf(g_B1lo);
    __nv_bfloat16* hhi[2] = {sym_addr_bf(g_hhiA), sym_addr_bf(g_hhiB)};
    __nv_bfloat16* hlo[2] = {sym_addr_bf(g_hloA), sym_addr_bf(g_hloB)};
    uint4* W1f4 = sym_addr_u4(g_W1f4);
    uint4* W2f4 = sym_addr_u4(g_W2f4);

    float* out = (float*)d_out;

    // ---- prep: weight packing/splitting ----
    bsplit1_kernel<<<(2 * 128 * 64 + 255) / 256, 256>>>(w1f_x, w1b_x);
    bsplit2_kernel<<<(2 * 128 * 576 + 255) / 256, 256>>>(w2f_x, w2b_x, Bhi, Blo);
    wfrag_kernel<<<(2 * 2 * 9 * 2 * 16 * 32 + 255) / 256, 256>>>(
        w1f_h, w1b_h, w2f_h, w2b_h);

    // ================= Layer 1: 48x56, Cin=6, F=32 ========================
    {
        gemm_xconv1<<<dim3(4032, 2), 256>>>(x, B1hi, B1lo, b1f, b1b, zb);
        const size_t hbytes = (size_t)2 * BB * 2688 * 32 * sizeof(__nv_bfloat16);
        cudaMemsetAsync(hhi[0], 0, hbytes);
        cudaMemsetAsync(hlo[0], 0, hbytes);
        cudaMemsetAsync(cp, 0, (size_t)2 * BB * 2688 * 32 * sizeof(float));
        for (int j = 0; j < TT; j++) {
            hconv_mma<48, 56, 1, 64, 6><<<dim3(48, BB, 2), 256>>>(
                zb, hhi[j & 1], hlo[j & 1], hhi[(j + 1) & 1], hlo[(j + 1) & 1],
                cp, W1f4, seq1, 64, j);
        }
        const size_t ptot = (size_t)BB * TT * 24 * 28 * 64;
        bnpool_kernel<<<(unsigned)((ptot + 255) / 256), 256>>>(
            seq1, p1, bn1_g, bn1_b, bn1_m, bn1_v, 48, 56, 64);
    }

    // ================= Layer 2: 24x28, Cin=64, F=32 =======================
    {
        const size_t itot = (size_t)129024 * 72;
        im2col2_kernel<<<(unsigned)((itot + 255) / 256), 256>>>(p1, Ahi, Alo);
        gemm_xconv2<<<dim3(1008, 2), 256>>>(Ahi, Alo, Bhi, Blo, b2f, b2b, zb);
        const size_t hbytes = (size_t)2 * BB * 672 * 32 * sizeof(__nv_bfloat16);
        cudaMemsetAsync(hhi[0], 0, hbytes);
        cudaMemsetAsync(hlo[0], 0, hbytes);
        cudaMemsetAsync(cp, 0, (size_t)2 * BB * 672 * 32 * sizeof(float));
        for (int j = 0; j < TT; j++) {
            hconv_mma<24, 28, 2, 32, 5><<<dim3(12, BB, 2), 256>>>(
                zb, hhi[j & 1], hlo[j & 1], hhi[(j + 1) & 1], hlo[(j + 1) & 1],
                cp, W2f4, seq2, 64, j);
        }
        const size_t ptot = (size_t)BB * TT * 12 * 14 * 64;
        bnpool_kernel<<<(unsigned)((ptot + 255) / 256), 256>>>(
            seq2, p2, bn2_g, bn2_b, bn2_m, bn2_v, 24, 28, 64);
    }

    // ================= Layer 3: 12x14, Cin=64, F=12 (persistent) ===========
    {
        xconv_all<64, 12, 12, 14, 4, 4><<<dim3(3, BB * TT, 2), 192>>>(
            p2, w3f_x, w3b_x, b3f, b3b, zb);
        lstm3_persistent<<<16, 288>>>(zb, w3f_h, w3b_h, out);
    }
}

// round 16
// speedup vs baseline: 1.0435x; 1.0435x over previous
#include <cuda_runtime.h>
#include <cuda_bf16.h>
#include <cstdint>
#include <math.h>

// ---------------------------------------------------------------------------
// Bidirectional 3-layer ConvLSTM encoder.
// L1/L2 serial h-conv on tensor cores (packed uint4 weight fragments),
// L1 x-conv scalar, L2 x-conv via FUSED implicit-im2col mma.sync GEMM
// (16-wide k-chunks lie inside one tap -> contiguous staging), L3 scalar.
// B=8, T=24. L1: 48x56 Cin=6 F=32. L2: 24x28 Cin=64 F=32. L3: 12x14 Cin=64 F=12.
// ---------------------------------------------------------------------------

#define BB 8
#define TT 24

// ---- scratch (__device__ globals) ----
__device__ __align__(16) float g_seq1[(size_t)BB * TT * 48 * 56 * 64];
__device__ __align__(16) float g_p1  [(size_t)BB * TT * 24 * 28 * 64];
__device__ __align__(16) float g_seq2[(size_t)BB * TT * 24 * 28 * 64];
__device__ __align__(16) float g_p2  [(size_t)BB * TT * 12 * 14 * 64];
__device__ __align__(16) float g_zbase[(size_t)2 * BB * TT * 48 * 56 * 128];
__device__ __align__(16) float g_c   [(size_t)2 * BB * 48 * 56 * 32];
// L2 xconv weights (bf16 hi/lo split, [dir][128][576])
__device__ __align__(16) __nv_bfloat16 g_Bhi[2 * 128 * 576];
__device__ __align__(16) __nv_bfloat16 g_Blo[2 * 128 * 576];
// h state as bf16 hi/lo, double-buffered (max size = L1)
__device__ __align__(16) __nv_bfloat16 g_hhiA[(size_t)2 * BB * 2688 * 32];
__device__ __align__(16) __nv_bfloat16 g_hloA[(size_t)2 * BB * 2688 * 32];
__device__ __align__(16) __nv_bfloat16 g_hhiB[(size_t)2 * BB * 2688 * 32];
__device__ __align__(16) __nv_bfloat16 g_hloB[(size_t)2 * BB * 2688 * 32];
// packed B-fragment tables: rec[(dir,tap,kc,nb8)][lane] = {bh0,bh1,bl0,bl1}
__device__ __align__(16) uint4 g_W1f4[2 * 9 * 2 * 16 * 32];
__device__ __align__(16) uint4 g_W2f4[2 * 9 * 2 * 16 * 32];

// ---------------------------------------------------------------------------
// mma.sync m16n8k16 bf16 (baseline PTX; conventions validated R9/R10).
// ---------------------------------------------------------------------------
__device__ __forceinline__ void mma_bf16(float c[4], const uint32_t a[4],
                                         const uint32_t b[2]) {
    asm volatile(
        "mma.sync.aligned.m16n8k16.row.col.f32.bf16.bf16.f32 "
        "{%0,%1,%2,%3}, {%4,%5,%6,%7}, {%8,%9}, {%0,%1,%2,%3};"
        : "+f"(c[0]), "+f"(c[1]), "+f"(c[2]), "+f"(c[3])
        : "r"(a[0]), "r"(a[1]), "r"(a[2]), "r"(a[3]), "r"(b[0]), "r"(b[1]));
}

// ---------------------------------------------------------------------------
// Prep: pack recurrent weights Wh[3,3,32,128] into per-lane uint4 fragment
// records (one LDG.128 per mma B-fragment).
// ---------------------------------------------------------------------------
__device__ __forceinline__ uint32_t pack_hi_pair(const float* src, int tap,
                                                 int kk, int oc) {
    const float w0 = src[(size_t)(tap * 32 + 2 * kk) * 128 + oc];
    const float w1 = src[(size_t)(tap * 32 + 2 * kk + 1) * 128 + oc];
    const __nv_bfloat16 h0 = __float2bfloat16_rn(w0);
    const __nv_bfloat16 h1 = __float2bfloat16_rn(w1);
    return (uint32_t)__bfloat16_as_ushort(h0) |
           ((uint32_t)__bfloat16_as_ushort(h1) << 16);
}
__device__ __forceinline__ uint32_t pack_lo_pair(const float* src, int tap,
                                                 int kk, int oc) {
    const float w0 = src[(size_t)(tap * 32 + 2 * kk) * 128 + oc];
    const float w1 = src[(size_t)(tap * 32 + 2 * kk + 1) * 128 + oc];
    const __nv_bfloat16 h0 = __float2bfloat16_rn(w0);
    const __nv_bfloat16 h1 = __float2bfloat16_rn(w1);
    const __nv_bfloat16 l0 = __float2bfloat16_rn(w0 - __bfloat162float(h0));
    const __nv_bfloat16 l1 = __float2bfloat16_rn(w1 - __bfloat162float(h1));
    return (uint32_t)__bfloat16_as_ushort(l0) |
           ((uint32_t)__bfloat16_as_ushort(l1) << 16);
}

__global__ void wfrag_kernel(const float* __restrict__ w1f,
                             const float* __restrict__ w1b,
                             const float* __restrict__ w2f,
                             const float* __restrict__ w2b) {
    int i = blockIdx.x * 256 + threadIdx.x;
    if (i >= 2 * 2 * 9 * 2 * 16 * 32) return;
    const int lane = i & 31;
    int r = i >> 5;
    const int nb8 = r & 15;
    r >>= 4;
    const int kc = r & 1;
    r >>= 1;
    const int tap = r % 9;
    r /= 9;
    const int dir = r & 1;
    const int layer = r >> 1;
    const float* src = layer ? (dir ? w2b : w2f) : (dir ? w1b : w1f);
    const int g = lane >> 2, t4 = lane & 3;
    const int oc = nb8 * 8 + g;
    const int kkA = kc * 8 + t4, kkB = kkA + 4;
    uint4 v;
    v.x = pack_hi_pair(src, tap, kkA, oc);
    v.y = pack_hi_pair(src, tap, kkB, oc);
    v.z = pack_lo_pair(src, tap, kkA, oc);
    v.w = pack_lo_pair(src, tap, kkB, oc);
    const size_t rec =
        ((((size_t)dir * 9 + tap) * 2 + kc) * 16 + nb8) * 32 + lane;
    (layer ? g_W2f4 : g_W1f4)[rec] = v;
}

// ---------------------------------------------------------------------------
// Serial h-conv step on tensor cores, fused gates (R13 design, unchanged).
// ---------------------------------------------------------------------------
template <int H, int W, int RPT, int XW, int XSH>
__global__ __launch_bounds__(256) void hconv_mma(
    const float* __restrict__ zbase,
    const __nv_bfloat16* __restrict__ hhi, const __nv_bfloat16* __restrict__ hlo,
    __nv_bfloat16* __restrict__ hhi_o, __nv_bfloat16* __restrict__ hlo_o,
    float* __restrict__ cstate,
    const uint4* __restrict__ Wf4,
    float* __restrict__ seq, int seqC, int j) {
    constexpr int HW = H * W;
    constexpr int SXW = XW + 2;
    constexpr int SPIX = (RPT + 2) * SXW;
    constexpr int PSW = 20;
    constexpr int ZS = 129;
    constexpr int A_BYTES = SPIX * PSW * 4 * 2;
    constexpr int Z_BYTES = RPT * XW * ZS * 4;
    constexpr int SBYTES = (A_BYTES > Z_BYTES) ? A_BYTES : Z_BYTES;
    __shared__ __align__(16) char smraw[SBYTES];
    uint32_t* sHh = (uint32_t*)smraw;
    uint32_t* sHl = sHh + SPIX * PSW;
    float* sZ = (float*)smraw;

    const int tid = threadIdx.x;
    const int dir = blockIdx.z, b = blockIdx.y;
    const int dirb = dir * BB + b;
    const int y0 = blockIdx.x * RPT;
    const int t = dir ? (TT - 1 - j) : j;

    const __nv_bfloat16* hhib = hhi + (size_t)dirb * HW * 32;
    const __nv_bfloat16* hlob = hlo + (size_t)dirb * HW * 32;
    for (int idx = tid; idx < SPIX * 16; idx += 256) {
        const int pix = idx >> 4, cw = idx & 15;
        const int sry = pix / SXW, sx = pix - sry * SXW;
        const int y = y0 + sry - 1, imx = sx - 1;
        uint32_t vh = 0, vl = 0;
        if (y >= 0 && y < H && imx >= 0 && imx < W) {
            const size_t o = ((size_t)(y * W + imx)) * 32 + cw * 2;
            vh = *(const uint32_t*)(hhib + o);
            vl = *(const uint32_t*)(hlob + o);
        }
        sHh[pix * PSW + cw] = vh;
        sHl[pix * PSW + cw] = vl;
    }
    __syncthreads();

    const int lane = tid & 31, wid = tid >> 5;
    const int warp_m = wid & 1, warp_n = wid >> 1;
    const int g = lane >> 2, t4 = lane & 3;

    float acc[2][4][4];
#pragma unroll
    for (int mb = 0; mb < 2; mb++)
#pragma unroll
        for (int nb = 0; nb < 4; nb++)
#pragma unroll
            for (int q = 0; q < 4; q++) acc[mb][nb][q] = 0.f;

    const uint4* Wd = Wf4 + (size_t)dir * 9 * 2 * 16 * 32;

    for (int tap = 0; tap < 9; tap++) {
        const int dy = tap / 3, dx = tap % 3;
#pragma unroll
        for (int kc = 0; kc < 2; kc++) {
            uint4 wv[4];
            {
                const uint4* base =
                    Wd + ((size_t)(tap * 2 + kc) * 16 + warp_n * 4) * 32 + lane;
#pragma unroll
                for (int nb = 0; nb < 4; nb++) wv[nb] = base[nb * 32];
            }
            uint32_t ah[2][4], al[2][4];
#pragma unroll
            for (int mb = 0; mb < 2; mb++) {
                const int r = warp_m * 32 + mb * 16 + g;
                const int r2 = r + 8;
                const int sp0 = ((r >> XSH) + dy) * SXW + (r & (XW - 1)) + dx;
                const int sp1 = ((r2 >> XSH) + dy) * SXW + (r2 & (XW - 1)) + dx;
                const int kw = kc * 8 + t4;
                ah[mb][0] = sHh[sp0 * PSW + kw];
                ah[mb][1] = sHh[sp1 * PSW + kw];
                ah[mb][2] = sHh[sp0 * PSW + kw + 4];
                ah[mb][3] = sHh[sp1 * PSW + kw + 4];
                al[mb][0] = sHl[sp0 * PSW + kw];
                al[mb][1] = sHl[sp1 * PSW + kw];
                al[mb][2] = sHl[sp0 * PSW + kw + 4];
                al[mb][3] = sHl[sp1 * PSW + kw + 4];
            }
#pragma unroll
            for (int nb = 0; nb < 4; nb++) {
                uint32_t bh[2] = {wv[nb].x, wv[nb].y};
                uint32_t bl[2] = {wv[nb].z, wv[nb].w};
#pragma unroll
                for (int mb = 0; mb < 2; mb++) {
                    mma_bf16(acc[mb][nb], ah[mb], bh);
                    mma_bf16(acc[mb][nb], ah[mb], bl);
                    mma_bf16(acc[mb][nb], al[mb], bh);
                }
            }
        }
    }

    __syncthreads();
#pragma unroll
    for (int mb = 0; mb < 2; mb++) {
        const int r = warp_m * 32 + mb * 16 + g;
#pragma unroll
        for (int nb = 0; nb < 4; nb++) {
            const int col = warp_n * 32 + nb * 8 + t4 * 2;
            sZ[r * ZS + col] = acc[mb][nb][0];
            sZ[r * ZS + col + 1] = acc[mb][nb][1];
            sZ[(r + 8) * ZS + col] = acc[mb][nb][2];
            sZ[(r + 8) * ZS + col + 1] = acc[mb][nb][3];
        }
    }
    __syncthreads();

    const float* zb = zbase + ((size_t)dirb * TT + t) * HW * 128;
    float* cb = cstate + (size_t)dirb * HW * 32;
    __nv_bfloat16* hho = hhi_o + (size_t)dirb * HW * 32;
    __nv_bfloat16* hlo_ob = hlo_o + (size_t)dirb * HW * 32;
    float* sq = seq + ((size_t)(b * TT + t)) * HW * seqC + dir * 32;
#pragma unroll
    for (int it = 0; it < (RPT * XW * 32) / 256; it++) {
        const int item = tid + it * 256;
        const int f = item & 31;
        const int m = item >> 5;
        const int x = m & (XW - 1);
        if (x >= W) continue;
        const int pf = (y0 + (m >> XSH)) * W + x;
        const float zi = sZ[m * ZS + f] + zb[(size_t)pf * 128 + f];
        const float zf2 = sZ[m * ZS + 32 + f] + zb[(size_t)pf * 128 + 32 + f];
        const float zg = sZ[m * ZS + 64 + f] + zb[(size_t)pf * 128 + 64 + f];
        const float zo = sZ[m * ZS + 96 + f] + zb[(size_t)pf * 128 + 96 + f];
        const float ig = fmaxf(zi, 0.f);
        const float fg = fmaxf(zf2, 0.f);
        const float gg = tanhf(zg);
        const float og = fmaxf(zo, 0.f);
        const float cn = fg * cb[(size_t)pf * 32 + f] + ig * gg;
        const float hn = og * tanhf(cn);
        cb[(size_t)pf * 32 + f] = cn;
        const __nv_bfloat16 hh = __float2bfloat16_rn(hn);
        hho[(size_t)pf * 32 + f] = hh;
        hlo_ob[(size_t)pf * 32 + f] =
            __float2bfloat16_rn(hn - __bfloat162float(hh));
        sq[(size_t)pf * seqC + f] = hn;
    }
}

// ---------------------------------------------------------------------------
// L2 xconv weight split ([dir][128 oc][576 k], k = tap*64 + c).
// ---------------------------------------------------------------------------
__global__ void bsplit2_kernel(const float* __restrict__ wf,
                               const float* __restrict__ wb,
                               __nv_bfloat16* __restrict__ Bhi,
                               __nv_bfloat16* __restrict__ Blo) {
    const int i = blockIdx.x * blockDim.x + threadIdx.x;
    if (i >= 2 * 128 * 576) return;
    const int dir = i / (128 * 576);
    const int r = i % (128 * 576);
    const int n = r / 576, k = r % 576;
    const float* w = dir ? wb : wf;
    const float v = w[(size_t)k * 128 + n];
    const __nv_bfloat16 hi = __float2bfloat16_rn(v);
    Bhi[i] = hi;
    Blo[i] = __float2bfloat16_rn(v - __bfloat162float(hi));
}

// ---------------------------------------------------------------------------
// L2 x-conv GEMM with FUSED implicit im2col.
//   zbase_dir[M=129024, 128] = im2col(p1)[M,576] x B_dir[128,576]^T + bias
// A staging: each 16-wide k-chunk lies inside ONE tap (16 | 64), so the
// per-thread stage is one bounds check + two aligned float4 loads from p1.
// grid = (1008, 2), block = 256 (8 warps: 4 M x 2 N).
// ---------------------------------------------------------------------------
__global__ __launch_bounds__(256) void gemm_xconv2(
    const float* __restrict__ p1,
    const __nv_bfloat16* __restrict__ Bhi, const __nv_bfloat16* __restrict__ Blo,
    const float* __restrict__ bias_f, const float* __restrict__ bias_b,
    float* __restrict__ zbase) {
    constexpr int RS = 24;
    __shared__ __align__(16) __nv_bfloat16 sAh[128 * RS];
    __shared__ __align__(16) __nv_bfloat16 sAl[128 * RS];
    __shared__ __align__(16) __nv_bfloat16 sBh[128 * RS];
    __shared__ __align__(16) __nv_bfloat16 sBl[128 * RS];

    const int tid = threadIdx.x;
    const int lane = tid & 31, wid = tid >> 5;
    const int warp_m = wid & 3, warp_n = wid >> 2;
    const int g = lane >> 2, t4 = lane & 3;
    const int tile = blockIdx.x, dir = blockIdx.y;
    const size_t m0 = (size_t)tile * 128;

    const __nv_bfloat16* Bh = Bhi + (size_t)dir * 128 * 576;
    const __nv_bfloat16* Bl = Blo + (size_t)dir * 128 * 576;
    const float* bias = dir ? bias_b : bias_f;

    float c[2][8][4];
#pragma unroll
    for (int mb = 0; mb < 2; mb++)
#pragma unroll
        for (int nb = 0; nb < 8; nb++)
#pragma unroll
            for (int q = 0; q < 4; q++) c[mb][nb][q] = 0.f;

    const int srow = tid & 127;
    const int shalf = tid >> 7;
    const int sdst = srow * RS + shalf * 8;

    // decode this thread's pixel once
    const int m = (int)m0 + srow;
    const int bt = m / 672;
    const int pos = m - bt * 672;
    const int py = pos / 28, px = pos - (pos / 28) * 28;
    const float* pb = p1 + (size_t)bt * 672 * 64;

    float a8[8];
    uint4 pBh, pBl;
    // prefetch chunk 0
    {
        const int yy = py - 1, xx = px - 1;  // tap 0
        const int c0 = shalf * 8;
        if (yy >= 0 && xx >= 0) {  // yy<24, xx<28 guaranteed for tap 0
            const float* s = pb + (size_t)(yy * 28 + xx) * 64 + c0;
            const float4 v0 = *(const float4*)s;
            const float4 v1 = *(const float4*)(s + 4);
            a8[0] = v0.x; a8[1] = v0.y; a8[2] = v0.z; a8[3] = v0.w;
            a8[4] = v1.x; a8[5] = v1.y; a8[6] = v1.z; a8[7] = v1.w;
        } else {
#pragma unroll
            for (int q = 0; q < 8; q++) a8[q] = 0.f;
        }
        pBh = *(const uint4*)(Bh + (size_t)srow * 576 + shalf * 8);
        pBl = *(const uint4*)(Bl + (size_t)srow * 576 + shalf * 8);
    }

    for (int kc = 0; kc < 36; kc++) {
        __syncthreads();
        // convert prefetched A to bf16 hi/lo and store
        {
            __nv_bfloat16 hi8[8], lo8[8];
#pragma unroll
            for (int q = 0; q < 8; q++) {
                hi8[q] = __float2bfloat16_rn(a8[q]);
                lo8[q] = __float2bfloat16_rn(a8[q] - __bfloat162float(hi8[q]));
            }
            *(uint4*)(sAh + sdst) = *(const uint4*)hi8;
            *(uint4*)(sAl + sdst) = *(const uint4*)lo8;
        }
        *(uint4*)(sBh + sdst) = pBh;
        *(uint4*)(sBl + sdst) = pBl;
        __syncthreads();
        if (kc + 1 < 36) {  // prefetch next chunk (overlapped with MMAs)
            const int kn = kc + 1;
            const int tap = kn >> 2;
            const int c0 = ((kn & 3) << 4) + shalf * 8;
            const int yy = py + tap / 3 - 1, xx = px + tap % 3 - 1;
            if (yy >= 0 && yy < 24 && xx >= 0 && xx < 28) {
                const float* s = pb + (size_t)(yy * 28 + xx) * 64 + c0;
                const float4 v0 = *(const float4*)s;
                const float4 v1 = *(const float4*)(s + 4);
                a8[0] = v0.x; a8[1] = v0.y; a8[2] = v0.z; a8[3] = v0.w;
                a8[4] = v1.x; a8[5] = v1.y; a8[6] = v1.z; a8[7] = v1.w;
            } else {
#pragma unroll
                for (int q = 0; q < 8; q++) a8[q] = 0.f;
            }
            const size_t ks = (size_t)kn * 16 + shalf * 8;
            pBh = *(const uint4*)(Bh + (size_t)srow * 576 + ks);
            pBl = *(const uint4*)(Bl + (size_t)srow * 576 + ks);
        }

        uint32_t ah[2][4], al[2][4];
#pragma unroll
        for (int mb = 0; mb < 2; mb++) {
            const int r0 = warp_m * 32 + mb * 16 + g;
            ah[mb][0] = *(const uint32_t*)(sAh + r0 * RS + t4 * 2);
            ah[mb][1] = *(const uint32_t*)(sAh + (r0 + 8) * RS + t4 * 2);
            ah[mb][2] = *(const uint32_t*)(sAh + r0 * RS + 8 + t4 * 2);
            ah[mb][3] = *(const uint32_t*)(sAh + (r0 + 8) * RS + 8 + t4 * 2);
            al[mb][0] = *(const uint32_t*)(sAl + r0 * RS + t4 * 2);
            al[mb][1] = *(const uint32_t*)(sAl + (r0 + 8) * RS + t4 * 2);
            al[mb][2] = *(const uint32_t*)(sAl + r0 * RS + 8 + t4 * 2);
            al[mb][3] = *(const uint32_t*)(sAl + (r0 + 8) * RS + 8 + t4 * 2);
        }
#pragma unroll
        for (int nb = 0; nb < 8; nb++) {
            const int n0 = warp_n * 64 + nb * 8 + g;
            uint32_t bh[2], bl[2];
            bh[0] = *(const uint32_t*)(sBh + n0 * RS + t4 * 2);
            bh[1] = *(const uint32_t*)(sBh + n0 * RS + 8 + t4 * 2);
            bl[0] = *(const uint32_t*)(sBl + n0 * RS + t4 * 2);
            bl[1] = *(const uint32_t*)(sBl + n0 * RS + 8 + t4 * 2);
#pragma unroll
            for (int mb = 0; mb < 2; mb++) {
                mma_bf16(c[mb][nb], ah[mb], bh);
                mma_bf16(c[mb][nb], ah[mb], bl);
                mma_bf16(c[mb][nb], al[mb], bh);
            }
        }
    }

    float* zd = zbase + ((size_t)dir * 129024 + m0) * 128;
#pragma unroll
    for (int mb = 0; mb < 2; mb++) {
        const int r0 = warp_m * 32 + mb * 16 + g;
#pragma unroll
        for (int nb = 0; nb < 8; nb++) {
            const int col = warp_n * 64 + nb * 8 + t4 * 2;
            zd[(size_t)r0 * 128 + col] = c[mb][nb][0] + bias[col];
            zd[(size_t)r0 * 128 + col + 1] = c[mb][nb][1] + bias[col + 1];
            zd[(size_t)(r0 + 8) * 128 + col] = c[mb][nb][2] + bias[col];
            zd[(size_t)(r0 + 8) * 128 + col + 1] = c[mb][nb][3] + bias[col + 1];
        }
    }
}

// ---------------------------------------------------------------------------
// Scalar x-conv over ALL timesteps (L1, L3).
// ---------------------------------------------------------------------------
template <int CIN, int F, int H, int W, int TH, int SUBS>
__global__ __launch_bounds__(SUBS * 4 * F) void xconv_all(
    const float* __restrict__ xin,
    const float* __restrict__ wxf, const float* __restrict__ wxb,
    const float* __restrict__ bf, const float* __restrict__ bb,
    float* __restrict__ zbase) {
    constexpr int OC = 4 * F;
    constexpr int NT = SUBS * OC;
    constexpr int THS = TH / SUBS;
    constexpr int TW = 14, TW2 = 16;
    constexpr int CSTRIDE = (TH + 2) * TW2 + 4;
    constexpr int TILES_W = W / TW;

    __shared__ __align__(16) float smem[CIN * CSTRIDE];

    const int dir = blockIdx.z;
    const int bt = blockIdx.y;
    const int tile = blockIdx.x;
    const int ty0 = (tile / TILES_W) * TH;
    const int tx0 = (tile % TILES_W) * TW;

    const float* wx = dir ? wxb : wxf;
    const float* bi = dir ? bb : bf;
    const float* xb = xin + (size_t)bt * H * W * CIN;
    const int b = bt / TT, t = bt % TT;

    const int tid = threadIdx.x;

    constexpr int TOTAL = (TH + 2) * TW2 * CIN;
    for (int idx = tid; idx < TOTAL; idx += NT) {
        int c = idx % CIN;
        int p = idx / CIN;
        int yy = p / TW2, xx = p % TW2;
        int gy = ty0 + yy - 1, gx = tx0 + xx - 1;
        float v = 0.f;
        if (gy >= 0 && gy < H && gx >= 0 && gx < W)
            v = xb[((size_t)gy * W + gx) * CIN + c];
        smem[c * CSTRIDE + yy * TW2 + xx] = v;
    }
    __syncthreads();

    const int oc = tid % OC;
    const int sub = tid / OC;

    float acc[THS][TW];
    {
        const float bv = bi[oc];
#pragma unroll
        for (int y = 0; y < THS; y++)
#pragma unroll
            for (int p = 0; p < TW; p++) acc[y][p] = bv;
    }

#pragma unroll 2
    for (int c = 0; c < CIN; c++) {
        const float* sc = smem + c * CSTRIDE + sub * THS * TW2;
        float w[9];
#pragma unroll
        for (int k = 0; k < 9; k++) w[k] = wx[((size_t)k * CIN + c) * OC + oc];
#pragma unroll
        for (int iy = 0; iy < THS + 2; iy++) {
            float seg[TW2];
#pragma unroll
            for (int q = 0; q < TW2 / 4; q++) {
                const float4 v =
                    *reinterpret_cast<const float4*>(sc + iy * TW2 + 4 * q);
                seg[4 * q] = v.x; seg[4 * q + 1] = v.y;
                seg[4 * q + 2] = v.z; seg[4 * q + 3] = v.w;
            }
#pragma unroll
            for (int dy = 0; dy < 3; dy++) {
                const int ry = iy - dy;
                if (ry >= 0 && ry < THS) {
#pragma unroll
                    for (int dx = 0; dx < 3; dx++) {
                        const float ww = w[dy * 3 + dx];
#pragma unroll
                        for (int p = 0; p < TW; p++)
                            acc[ry][p] = fmaf(ww, seg[p + dx], acc[ry][p]);
                    }
                }
            }
        }
    }

    float* zb = zbase + (((size_t)(dir * BB + b) * TT + t) * H * W +
                         (size_t)ty0 * W + tx0) * OC;
#pragma unroll
    for (int y = 0; y < THS; y++)
#pragma unroll
        for (int p = 0; p < TW; p++)
            zb[((size_t)(sub * THS + y) * W + p) * OC + oc] = acc[y][p];
}

// ---------------------------------------------------------------------------
// Layer 3 persistent kernel.
// ---------------------------------------------------------------------------
__global__ __launch_bounds__(288) void lstm3_persistent(
    const float* __restrict__ zbase,
    const float* __restrict__ whf, const float* __restrict__ whb,
    float* __restrict__ out) {
    constexpr int F = 12, OC = 48, H = 12, W = 14, HW = H * W;
    constexpr int TW2 = 16, CSTR = (H + 2) * TW2 + 4;

    __shared__ __align__(16) float sh[F * CSTR];
    __shared__ __align__(16) float sz[HW * OC];

    const int dirb = blockIdx.x;
    const int dir = dirb / BB;
    const int b = dirb % BB;
    const float* wh = dir ? whb : whf;
    const int tid = threadIdx.x;

    for (int i = tid; i < F * CSTR; i += 288) sh[i] = 0.f;

    const int f = tid % F;
    const int pidx = tid / F;
    float creg[7];
#pragma unroll
    for (int k = 0; k < 7; k++) creg[k] = 0.f;

    const int oc = tid % OC;
    const int sub = tid / OC;

    for (int j = 0; j < TT; j++) {
        const int t = dir ? (TT - 1 - j) : j;
        __syncthreads();

        const float* zb = zbase + ((size_t)dirb * TT + t) * HW * OC;
        float acc[2][14];
#pragma unroll
        for (int y = 0; y < 2; y++)
#pragma unroll
            for (int p = 0; p < 14; p++)
                acc[y][p] = zb[((sub * 2 + y) * W + p) * OC + oc];

#pragma unroll
        for (int c = 0; c < F; c++) {
            const float* sc = sh + c * CSTR + sub * 2 * TW2;
            float w[9];
#pragma unroll
            for (int k = 0; k < 9; k++) w[k] = wh[((size_t)k * F + c) * OC + oc];
#pragma unroll
            for (int iy = 0; iy < 4; iy++) {
                float seg[16];
#pragma unroll
                for (int q = 0; q < 4; q++) {
                    const float4 v =
                        *reinterpret_cast<const float4*>(sc + iy * TW2 + 4 * q);
                    seg[4 * q] = v.x; seg[4 * q + 1] = v.y;
                    seg[4 * q + 2] = v.z; seg[4 * q + 3] = v.w;
                }
#pragma unroll
                for (int dy = 0; dy < 3; dy++) {
                    const int ry = iy - dy;
                    if (ry >= 0 && ry < 2) {
#pragma unroll
                        for (int dx = 0; dx < 3; dx++) {
                            const float ww = w[dy * 3 + dx];
#pragma unroll
                            for (int p = 0; p < 14; p++)
                                acc[ry][p] = fmaf(ww, seg[p + dx], acc[ry][p]);
                        }
                    }
                }
            }
        }

        __syncthreads();
#pragma unroll
        for (int y = 0; y < 2; y++)
#pragma unroll
            for (int p = 0; p < 14; p++)
                sz[((sub * 2 + y) * W + p) * OC + oc] = acc[y][p];
        __syncthreads();

        float* sq = out + ((size_t)(b * TT + t) * HW) * 24 + dir * F;
#pragma unroll
        for (int k = 0; k < 7; k++) {
            const int pos = pidx + 24 * k;
            const float zi = sz[pos * OC + f];
            const float zf = sz[pos * OC + F + f];
            const float zg = sz[pos * OC + 2 * F + f];
            const float zo = sz[pos * OC + 3 * F + f];
            const float ig = fmaxf(zi, 0.f);
            const float fg = fmaxf(zf, 0.f);
            const float gg = tanhf(zg);
            const float og = fmaxf(zo, 0.f);
            const float cn = fg * creg[k] + ig * gg;
            const float hn = og * tanhf(cn);
            creg[k] = cn;
            sq[pos * 24 + f] = hn;
            const int y = pos / W, x = pos % W;
            sh[f * CSTR + (y + 1) * TW2 + (x + 1)] = hn;
        }
    }

    __syncthreads();
    const size_t SEQ3 = (size_t)BB * TT * HW * 24;
    const size_t ST3 = (size_t)BB * HW * F;
    float* oh = out + SEQ3 + (size_t)(2 * dir) * ST3;
    float* ocst = out + SEQ3 + (size_t)(2 * dir + 1) * ST3;
#pragma unroll
    for (int k = 0; k < 7; k++) {
        const int pos = pidx + 24 * k;
        const int y = pos / W, x = pos % W;
        oh[((size_t)b * HW + pos) * F + f] = sh[f * CSTR + (y + 1) * TW2 + (x + 1)];
        ocst[((size_t)b * HW + pos) * F + f] = creg[k];
    }
}

// ---------------------------------------------------------------------------
// BN (eps=1e-3) then 2x2 max pool.
// ---------------------------------------------------------------------------
__global__ void bnpool_kernel(const float* __restrict__ in,
                              float* __restrict__ out,
                              const float* __restrict__ gg,
                              const float* __restrict__ bb,
                              const float* __restrict__ mm,
                              const float* __restrict__ vv, int H, int W,
                              int C) {
    const int HO = H / 2, WO = W / 2;
    const size_t total = (size_t)BB * TT * HO * WO * C;
    size_t i = (size_t)blockIdx.x * blockDim.x + threadIdx.x;
    if (i >= total) return;
    const int c = i % C;
    size_t r = i / C;
    const int x = r % WO;
    r /= WO;
    const int y = r % HO;
    r /= HO;
    const int t = r % TT;
    const int b = r / TT;

    const float scale = gg[c] * rsqrtf(vv[c] + 1e-3f);
    const float shift = bb[c] - mm[c] * scale;

    const float* base = in + ((size_t)(b * TT + t)) * H * W * C;
    float mx = -3.402823e38f;
#pragma unroll
    for (int dy = 0; dy < 2; dy++)
#pragma unroll
        for (int dx = 0; dx < 2; dx++) {
            float v =
                base[((size_t)(2 * y + dy) * W + (2 * x + dx)) * C + c] * scale +
                shift;
            mx = fmaxf(mx, v);
        }
    out[i] = mx;
}

// ---------------------------------------------------------------------------
// Host side
// ---------------------------------------------------------------------------
static float* sym_addr(const void* symbol) {
    void* p = nullptr;
    cudaGetSymbolAddress(&p, symbol);
    return (float*)p;
}
static __nv_bfloat16* sym_addr_bf(const void* symbol) {
    void* p = nullptr;
    cudaGetSymbolAddress(&p, symbol);
    return (__nv_bfloat16*)p;
}
static uint4* sym_addr_u4(const void* symbol) {
    void* p = nullptr;
    cudaGetSymbolAddress(&p, symbol);
    return (uint4*)p;
}

extern "C" void kernel_launch(void* const* d_in, const int* in_sizes, int n_in,
                              void* d_out, int out_size) {
    const float* x = (const float*)d_in[0];
    const float* w1f_x = (const float*)d_in[1];
    const float* w1f_h = (const float*)d_in[2];
    const float* b1f = (const float*)d_in[3];
    const float* w1b_x = (const float*)d_in[4];
    const float* w1b_h = (const float*)d_in[5];
    const float* b1b = (const float*)d_in[6];
    const float* w2f_x = (const float*)d_in[7];
    const float* w2f_h = (const float*)d_in[8];
    const float* b2f = (const float*)d_in[9];
    const float* w2b_x = (const float*)d_in[10];
    const float* w2b_h = (const float*)d_in[11];
    const float* b2b = (const float*)d_in[12];
    const float* w3f_x = (const float*)d_in[13];
    const float* w3f_h = (const float*)d_in[14];
    const float* b3f = (const float*)d_in[15];
    const float* w3b_x = (const float*)d_in[16];
    const float* w3b_h = (const float*)d_in[17];
    const float* b3b = (const float*)d_in[18];
    const float* bn1_g = (const float*)d_in[19];
    const float* bn1_b = (const float*)d_in[20];
    const float* bn1_m = (const float*)d_in[21];
    const float* bn1_v = (const float*)d_in[22];
    const float* bn2_g = (const float*)d_in[23];
    const float* bn2_b = (const float*)d_in[24];
    const float* bn2_m = (const float*)d_in[25];
    const float* bn2_v = (const float*)d_in[26];

    float* seq1 = sym_addr(g_seq1);
    float* p1 = sym_addr(g_p1);
    float* seq2 = sym_addr(g_seq2);
    float* p2 = sym_addr(g_p2);
    float* zb = sym_addr(g_zbase);
    float* cp = sym_addr(g_c);
    __nv_bfloat16* Bhi = sym_addr_bf(g_Bhi);
    __nv_bfloat16* Blo = sym_addr_bf(g_Blo);
    __nv_bfloat16* hhi[2] = {sym_addr_bf(g_hhiA), sym_addr_bf(g_hhiB)};
    __nv_bfloat16* hlo[2] = {sym_addr_bf(g_hloA), sym_addr_bf(g_hloB)};
    uint4* W1f4 = sym_addr_u4(g_W1f4);
    uint4* W2f4 = sym_addr_u4(g_W2f4);

    float* out = (float*)d_out;

    // ---- prep: weight packing/splitting ----
    bsplit2_kernel<<<(2 * 128 * 576 + 255) / 256, 256>>>(w2f_x, w2b_x, Bhi, Blo);
    wfrag_kernel<<<(2 * 2 * 9 * 2 * 16 * 32 + 255) / 256, 256>>>(
        w1f_h, w1b_h, w2f_h, w2b_h);

    // ================= Layer 1: 48x56, Cin=6, F=32 ========================
    {
        xconv_all<6, 32, 48, 56, 4, 2><<<dim3(48, BB * TT, 2), 256>>>(
            x, w1f_x, w1b_x, b1f, b1b, zb);
        const size_t hbytes = (size_t)2 * BB * 2688 * 32 * sizeof(__nv_bfloat16);
        cudaMemsetAsync(hhi[0], 0, hbytes);
        cudaMemsetAsync(hlo[0], 0, hbytes);
        cudaMemsetAsync(cp, 0, (size_t)2 * BB * 2688 * 32 * sizeof(float));
        for (int j = 0; j < TT; j++) {
            hconv_mma<48, 56, 1, 64, 6><<<dim3(48, BB, 2), 256>>>(
                zb, hhi[j & 1], hlo[j & 1], hhi[(j + 1) & 1], hlo[(j + 1) & 1],
                cp, W1f4, seq1, 64, j);
        }
        const size_t ptot = (size_t)BB * TT * 24 * 28 * 64;
        bnpool_kernel<<<(unsigned)((ptot + 255) / 256), 256>>>(
            seq1, p1, bn1_g, bn1_b, bn1_m, bn1_v, 48, 56, 64);
    }

    // ================= Layer 2: 24x28, Cin=64, F=32 =======================
    {
        gemm_xconv2<<<dim3(1008, 2), 256>>>(p1, Bhi, Blo, b2f, b2b, zb);
        const size_t hbytes = (size_t)2 * BB * 672 * 32 * sizeof(__nv_bfloat16);
        cudaMemsetAsync(hhi[0], 0, hbytes);
        cudaMemsetAsync(hlo[0], 0, hbytes);
        cudaMemsetAsync(cp, 0, (size_t)2 * BB * 672 * 32 * sizeof(float));
        for (int j = 0; j < TT; j++) {
            hconv_mma<24, 28, 2, 32, 5><<<dim3(12, BB, 2), 256>>>(
                zb, hhi[j & 1], hlo[j & 1], hhi[(j + 1) & 1], hlo[(j + 1) & 1],
                cp, W2f4, seq2, 64, j);
        }
        const size_t ptot = (size_t)BB * TT * 12 * 14 * 64;
        bnpool_kernel<<<(unsigned)((ptot + 255) / 256), 256>>>(
            seq2, p2, bn2_g, bn2_b, bn2_m, bn2_v, 24, 28, 64);
    }

    // ================= Layer 3: 12x14, Cin=64, F=12 (persistent) ===========
    {
        xconv_all<64, 12, 12, 14, 4, 4><<<dim3(3, BB * TT, 2), 192>>>(
            p2, w3f_x, w3b_x, b3f, b3b, zb);
        lstm3_persistent<<<16, 288>>>(zb, w3f_h, w3b_h, out);
    }
}

// round 17
// speedup vs baseline: 1.0780x; 1.0331x over previous
#include <cuda_runtime.h>
#include <cuda_bf16.h>
#include <cstdint>
#include <math.h>

// ---------------------------------------------------------------------------
// Bidirectional 3-layer ConvLSTM encoder.
// L1/L2 serial h-conv on tensor cores (packed uint4 weight fragments; MB
// templated so L2 runs RPT=1 for 2x grid parallelism),
// L1 x-conv scalar, L2 x-conv via FUSED implicit-im2col mma.sync GEMM,
// L3 scalar persistent.
// B=8, T=24. L1: 48x56 Cin=6 F=32. L2: 24x28 Cin=64 F=32. L3: 12x14 Cin=64 F=12.
// ---------------------------------------------------------------------------

#define BB 8
#define TT 24

// ---- scratch (__device__ globals) ----
__device__ __align__(16) float g_seq1[(size_t)BB * TT * 48 * 56 * 64];
__device__ __align__(16) float g_p1  [(size_t)BB * TT * 24 * 28 * 64];
__device__ __align__(16) float g_seq2[(size_t)BB * TT * 24 * 28 * 64];
__device__ __align__(16) float g_p2  [(size_t)BB * TT * 12 * 14 * 64];
__device__ __align__(16) float g_zbase[(size_t)2 * BB * TT * 48 * 56 * 128];
__device__ __align__(16) float g_c   [(size_t)2 * BB * 48 * 56 * 32];
// L2 xconv weights (bf16 hi/lo split, [dir][128][576])
__device__ __align__(16) __nv_bfloat16 g_Bhi[2 * 128 * 576];
__device__ __align__(16) __nv_bfloat16 g_Blo[2 * 128 * 576];
// h state as bf16 hi/lo, double-buffered (max size = L1)
__device__ __align__(16) __nv_bfloat16 g_hhiA[(size_t)2 * BB * 2688 * 32];
__device__ __align__(16) __nv_bfloat16 g_hloA[(size_t)2 * BB * 2688 * 32];
__device__ __align__(16) __nv_bfloat16 g_hhiB[(size_t)2 * BB * 2688 * 32];
__device__ __align__(16) __nv_bfloat16 g_hloB[(size_t)2 * BB * 2688 * 32];
// packed B-fragment tables: rec[(dir,tap,kc,nb8)][lane] = {bh0,bh1,bl0,bl1}
__device__ __align__(16) uint4 g_W1f4[2 * 9 * 2 * 16 * 32];
__device__ __align__(16) uint4 g_W2f4[2 * 9 * 2 * 16 * 32];

// ---------------------------------------------------------------------------
// mma.sync m16n8k16 bf16 (baseline PTX; conventions validated R9/R10).
// ---------------------------------------------------------------------------
__device__ __forceinline__ void mma_bf16(float c[4], const uint32_t a[4],
                                         const uint32_t b[2]) {
    asm volatile(
        "mma.sync.aligned.m16n8k16.row.col.f32.bf16.bf16.f32 "
        "{%0,%1,%2,%3}, {%4,%5,%6,%7}, {%8,%9}, {%0,%1,%2,%3};"
        : "+f"(c[0]), "+f"(c[1]), "+f"(c[2]), "+f"(c[3])
        : "r"(a[0]), "r"(a[1]), "r"(a[2]), "r"(a[3]), "r"(b[0]), "r"(b[1]));
}

// ---------------------------------------------------------------------------
// Prep: pack recurrent weights Wh[3,3,32,128] into per-lane uint4 fragment
// records (one LDG.128 per mma B-fragment).
// ---------------------------------------------------------------------------
__device__ __forceinline__ uint32_t pack_hi_pair(const float* src, int tap,
                                                 int kk, int oc) {
    const float w0 = src[(size_t)(tap * 32 + 2 * kk) * 128 + oc];
    const float w1 = src[(size_t)(tap * 32 + 2 * kk + 1) * 128 + oc];
    const __nv_bfloat16 h0 = __float2bfloat16_rn(w0);
    const __nv_bfloat16 h1 = __float2bfloat16_rn(w1);
    return (uint32_t)__bfloat16_as_ushort(h0) |
           ((uint32_t)__bfloat16_as_ushort(h1) << 16);
}
__device__ __forceinline__ uint32_t pack_lo_pair(const float* src, int tap,
                                                 int kk, int oc) {
    const float w0 = src[(size_t)(tap * 32 + 2 * kk) * 128 + oc];
    const float w1 = src[(size_t)(tap * 32 + 2 * kk + 1) * 128 + oc];
    const __nv_bfloat16 h0 = __float2bfloat16_rn(w0);
    const __nv_bfloat16 h1 = __float2bfloat16_rn(w1);
    const __nv_bfloat16 l0 = __float2bfloat16_rn(w0 - __bfloat162float(h0));
    const __nv_bfloat16 l1 = __float2bfloat16_rn(w1 - __bfloat162float(h1));
    return (uint32_t)__bfloat16_as_ushort(l0) |
           ((uint32_t)__bfloat16_as_ushort(l1) << 16);
}

__global__ void wfrag_kernel(const float* __restrict__ w1f,
                             const float* __restrict__ w1b,
                             const float* __restrict__ w2f,
                             const float* __restrict__ w2b) {
    int i = blockIdx.x * 256 + threadIdx.x;
    if (i >= 2 * 2 * 9 * 2 * 16 * 32) return;
    const int lane = i & 31;
    int r = i >> 5;
    const int nb8 = r & 15;
    r >>= 4;
    const int kc = r & 1;
    r >>= 1;
    const int tap = r % 9;
    r /= 9;
    const int dir = r & 1;
    const int layer = r >> 1;
    const float* src = layer ? (dir ? w2b : w2f) : (dir ? w1b : w1f);
    const int g = lane >> 2, t4 = lane & 3;
    const int oc = nb8 * 8 + g;
    const int kkA = kc * 8 + t4, kkB = kkA + 4;
    uint4 v;
    v.x = pack_hi_pair(src, tap, kkA, oc);
    v.y = pack_hi_pair(src, tap, kkB, oc);
    v.z = pack_lo_pair(src, tap, kkA, oc);
    v.w = pack_lo_pair(src, tap, kkB, oc);
    const size_t rec =
        ((((size_t)dir * 9 + tap) * 2 + kc) * 16 + nb8) * 32 + lane;
    (layer ? g_W2f4 : g_W1f4)[rec] = v;
}

// ---------------------------------------------------------------------------
// Serial h-conv step on tensor cores, fused gates.  M = RPT*XW = MB*2*16 px.
// grid (H/RPT, B, 2dir), block 256 (8 warps: 2 along M x 4 along N).
// ---------------------------------------------------------------------------
template <int H, int W, int RPT, int XW, int XSH, int MB>
__global__ __launch_bounds__(256) void hconv_mma(
    const float* __restrict__ zbase,
    const __nv_bfloat16* __restrict__ hhi, const __nv_bfloat16* __restrict__ hlo,
    __nv_bfloat16* __restrict__ hhi_o, __nv_bfloat16* __restrict__ hlo_o,
    float* __restrict__ cstate,
    const uint4* __restrict__ Wf4,
    float* __restrict__ seq, int seqC, int j) {
    constexpr int HW = H * W;
    constexpr int SXW = XW + 2;
    constexpr int SPIX = (RPT + 2) * SXW;
    constexpr int PSW = 20;
    constexpr int ZS = 129;
    constexpr int A_BYTES = SPIX * PSW * 4 * 2;
    constexpr int Z_BYTES = RPT * XW * ZS * 4;
    constexpr int SBYTES = (A_BYTES > Z_BYTES) ? A_BYTES : Z_BYTES;
    __shared__ __align__(16) char smraw[SBYTES];
    uint32_t* sHh = (uint32_t*)smraw;
    uint32_t* sHl = sHh + SPIX * PSW;
    float* sZ = (float*)smraw;

    const int tid = threadIdx.x;
    const int dir = blockIdx.z, b = blockIdx.y;
    const int dirb = dir * BB + b;
    const int y0 = blockIdx.x * RPT;
    const int t = dir ? (TT - 1 - j) : j;

    const __nv_bfloat16* hhib = hhi + (size_t)dirb * HW * 32;
    const __nv_bfloat16* hlob = hlo + (size_t)dirb * HW * 32;
    for (int idx = tid; idx < SPIX * 16; idx += 256) {
        const int pix = idx >> 4, cw = idx & 15;
        const int sry = pix / SXW, sx = pix - sry * SXW;
        const int y = y0 + sry - 1, imx = sx - 1;
        uint32_t vh = 0, vl = 0;
        if (y >= 0 && y < H && imx >= 0 && imx < W) {
            const size_t o = ((size_t)(y * W + imx)) * 32 + cw * 2;
            vh = *(const uint32_t*)(hhib + o);
            vl = *(const uint32_t*)(hlob + o);
        }
        sHh[pix * PSW + cw] = vh;
        sHl[pix * PSW + cw] = vl;
    }
    __syncthreads();

    const int lane = tid & 31, wid = tid >> 5;
    const int warp_m = wid & 1, warp_n = wid >> 1;
    const int g = lane >> 2, t4 = lane & 3;

    float acc[MB][4][4];
#pragma unroll
    for (int mb = 0; mb < MB; mb++)
#pragma unroll
        for (int nb = 0; nb < 4; nb++)
#pragma unroll
            for (int q = 0; q < 4; q++) acc[mb][nb][q] = 0.f;

    const uint4* Wd = Wf4 + (size_t)dir * 9 * 2 * 16 * 32;

    for (int tap = 0; tap < 9; tap++) {
        const int dy = tap / 3, dx = tap % 3;
#pragma unroll
        for (int kc = 0; kc < 2; kc++) {
            uint4 wv[4];
            {
                const uint4* base =
                    Wd + ((size_t)(tap * 2 + kc) * 16 + warp_n * 4) * 32 + lane;
#pragma unroll
                for (int nb = 0; nb < 4; nb++) wv[nb] = base[nb * 32];
            }
            uint32_t ah[MB][4], al[MB][4];
#pragma unroll
            for (int mb = 0; mb < MB; mb++) {
                const int r = warp_m * (MB * 16) + mb * 16 + g;
                const int r2 = r + 8;
                const int sp0 = ((r >> XSH) + dy) * SXW + (r & (XW - 1)) + dx;
                const int sp1 = ((r2 >> XSH) + dy) * SXW + (r2 & (XW - 1)) + dx;
                const int kw = kc * 8 + t4;
                ah[mb][0] = sHh[sp0 * PSW + kw];
                ah[mb][1] = sHh[sp1 * PSW + kw];
                ah[mb][2] = sHh[sp0 * PSW + kw + 4];
                ah[mb][3] = sHh[sp1 * PSW + kw + 4];
                al[mb][0] = sHl[sp0 * PSW + kw];
                al[mb][1] = sHl[sp1 * PSW + kw];
                al[mb][2] = sHl[sp0 * PSW + kw + 4];
                al[mb][3] = sHl[sp1 * PSW + kw + 4];
            }
#pragma unroll
            for (int nb = 0; nb < 4; nb++) {
                uint32_t bh[2] = {wv[nb].x, wv[nb].y};
                uint32_t bl[2] = {wv[nb].z, wv[nb].w};
#pragma unroll
                for (int mb = 0; mb < MB; mb++) {
                    mma_bf16(acc[mb][nb], ah[mb], bh);
                    mma_bf16(acc[mb][nb], ah[mb], bl);
                    mma_bf16(acc[mb][nb], al[mb], bh);
                }
            }
        }
    }

    __syncthreads();
#pragma unroll
    for (int mb = 0; mb < MB; mb++) {
        const int r = warp_m * (MB * 16) + mb * 16 + g;
#pragma unroll
        for (int nb = 0; nb < 4; nb++) {
            const int col = warp_n * 32 + nb * 8 + t4 * 2;
            sZ[r * ZS + col] = acc[mb][nb][0];
            sZ[r * ZS + col + 1] = acc[mb][nb][1];
            sZ[(r + 8) * ZS + col] = acc[mb][nb][2];
            sZ[(r + 8) * ZS + col + 1] = acc[mb][nb][3];
        }
    }
    __syncthreads();

    const float* zb = zbase + ((size_t)dirb * TT + t) * HW * 128;
    float* cb = cstate + (size_t)dirb * HW * 32;
    __nv_bfloat16* hho = hhi_o + (size_t)dirb * HW * 32;
    __nv_bfloat16* hlo_ob = hlo_o + (size_t)dirb * HW * 32;
    float* sq = seq + ((size_t)(b * TT + t)) * HW * seqC + dir * 32;
#pragma unroll
    for (int it = 0; it < (RPT * XW * 32) / 256; it++) {
        const int item = tid + it * 256;
        const int f = item & 31;
        const int m = item >> 5;
        const int x = m & (XW - 1);
        if (x >= W) continue;
        const int pf = (y0 + (m >> XSH)) * W + x;
        const float zi = sZ[m * ZS + f] + zb[(size_t)pf * 128 + f];
        const float zf2 = sZ[m * ZS + 32 + f] + zb[(size_t)pf * 128 + 32 + f];
        const float zg = sZ[m * ZS + 64 + f] + zb[(size_t)pf * 128 + 64 + f];
        const float zo = sZ[m * ZS + 96 + f] + zb[(size_t)pf * 128 + 96 + f];
        const float ig = fmaxf(zi, 0.f);
        const float fg = fmaxf(zf2, 0.f);
        const float gg = tanhf(zg);
        const float og = fmaxf(zo, 0.f);
        const float cn = fg * cb[(size_t)pf * 32 + f] + ig * gg;
        const float hn = og * tanhf(cn);
        cb[(size_t)pf * 32 + f] = cn;
        const __nv_bfloat16 hh = __float2bfloat16_rn(hn);
        hho[(size_t)pf * 32 + f] = hh;
        hlo_ob[(size_t)pf * 32 + f] =
            __float2bfloat16_rn(hn - __bfloat162float(hh));
        sq[(size_t)pf * seqC + f] = hn;
    }
}

// ---------------------------------------------------------------------------
// L2 xconv weight split ([dir][128 oc][576 k], k = tap*64 + c).
// ---------------------------------------------------------------------------
__global__ void bsplit2_kernel(const float* __restrict__ wf,
                               const float* __restrict__ wb,
                               __nv_bfloat16* __restrict__ Bhi,
                               __nv_bfloat16* __restrict__ Blo) {
    const int i = blockIdx.x * blockDim.x + threadIdx.x;
    if (i >= 2 * 128 * 576) return;
    const int dir = i / (128 * 576);
    const int r = i % (128 * 576);
    const int n = r / 576, k = r % 576;
    const float* w = dir ? wb : wf;
    const float v = w[(size_t)k * 128 + n];
    const __nv_bfloat16 hi = __float2bfloat16_rn(v);
    Bhi[i] = hi;
    Blo[i] = __float2bfloat16_rn(v - __bfloat162float(hi));
}

// ---------------------------------------------------------------------------
// L2 x-conv GEMM with FUSED implicit im2col (R16 design, unchanged).
// ---------------------------------------------------------------------------
__global__ __launch_bounds__(256) void gemm_xconv2(
    const float* __restrict__ p1,
    const __nv_bfloat16* __restrict__ Bhi, const __nv_bfloat16* __restrict__ Blo,
    const float* __restrict__ bias_f, const float* __restrict__ bias_b,
    float* __restrict__ zbase) {
    constexpr int RS = 24;
    __shared__ __align__(16) __nv_bfloat16 sAh[128 * RS];
    __shared__ __align__(16) __nv_bfloat16 sAl[128 * RS];
    __shared__ __align__(16) __nv_bfloat16 sBh[128 * RS];
    __shared__ __align__(16) __nv_bfloat16 sBl[128 * RS];

    const int tid = threadIdx.x;
    const int lane = tid & 31, wid = tid >> 5;
    const int warp_m = wid & 3, warp_n = wid >> 2;
    const int g = lane >> 2, t4 = lane & 3;
    const int tile = blockIdx.x, dir = blockIdx.y;
    const size_t m0 = (size_t)tile * 128;

    const __nv_bfloat16* Bh = Bhi + (size_t)dir * 128 * 576;
    const __nv_bfloat16* Bl = Blo + (size_t)dir * 128 * 576;
    const float* bias = dir ? bias_b : bias_f;

    float c[2][8][4];
#pragma unroll
    for (int mb = 0; mb < 2; mb++)
#pragma unroll
        for (int nb = 0; nb < 8; nb++)
#pragma unroll
            for (int q = 0; q < 4; q++) c[mb][nb][q] = 0.f;

    const int srow = tid & 127;
    const int shalf = tid >> 7;
    const int sdst = srow * RS + shalf * 8;

    const int m = (int)m0 + srow;
    const int bt = m / 672;
    const int pos = m - bt * 672;
    const int py = pos / 28, px = pos - (pos / 28) * 28;
    const float* pb = p1 + (size_t)bt * 672 * 64;

    float a8[8];
    uint4 pBh, pBl;
    {
        const int yy = py - 1, xx = px - 1;  // tap 0
        const int c0 = shalf * 8;
        if (yy >= 0 && xx >= 0) {
            const float* s = pb + (size_t)(yy * 28 + xx) * 64 + c0;
            const float4 v0 = *(const float4*)s;
            const float4 v1 = *(const float4*)(s + 4);
            a8[0] = v0.x; a8[1] = v0.y; a8[2] = v0.z; a8[3] = v0.w;
            a8[4] = v1.x; a8[5] = v1.y; a8[6] = v1.z; a8[7] = v1.w;
        } else {
#pragma unroll
            for (int q = 0; q < 8; q++) a8[q] = 0.f;
        }
        pBh = *(const uint4*)(Bh + (size_t)srow * 576 + shalf * 8);
        pBl = *(const uint4*)(Bl + (size_t)srow * 576 + shalf * 8);
    }

    for (int kc = 0; kc < 36; kc++) {
        __syncthreads();
        {
            __nv_bfloat16 hi8[8], lo8[8];
#pragma unroll
            for (int q = 0; q < 8; q++) {
                hi8[q] = __float2bfloat16_rn(a8[q]);
                lo8[q] = __float2bfloat16_rn(a8[q] - __bfloat162float(hi8[q]));
            }
            *(uint4*)(sAh + sdst) = *(const uint4*)hi8;
            *(uint4*)(sAl + sdst) = *(const uint4*)lo8;
        }
        *(uint4*)(sBh + sdst) = pBh;
        *(uint4*)(sBl + sdst) = pBl;
        __syncthreads();
        if (kc + 1 < 36) {
            const int kn = kc + 1;
            const int tap = kn >> 2;
            const int c0 = ((kn & 3) << 4) + shalf * 8;
            const int yy = py + tap / 3 - 1, xx = px + tap % 3 - 1;
            if (yy >= 0 && yy < 24 && xx >= 0 && xx < 28) {
                const float* s = pb + (size_t)(yy * 28 + xx) * 64 + c0;
                const float4 v0 = *(const float4*)s;
                const float4 v1 = *(const float4*)(s + 4);
                a8[0] = v0.x; a8[1] = v0.y; a8[2] = v0.z; a8[3] = v0.w;
                a8[4] = v1.x; a8[5] = v1.y; a8[6] = v1.z; a8[7] = v1.w;
            } else {
#pragma unroll
                for (int q = 0; q < 8; q++) a8[q] = 0.f;
            }
            const size_t ks = (size_t)kn * 16 + shalf * 8;
            pBh = *(const uint4*)(Bh + (size_t)srow * 576 + ks);
            pBl = *(const uint4*)(Bl + (size_t)srow * 576 + ks);
        }

        uint32_t ah[2][4], al[2][4];
#pragma unroll
        for (int mb = 0; mb < 2; mb++) {
            const int r0 = warp_m * 32 + mb * 16 + g;
            ah[mb][0] = *(const uint32_t*)(sAh + r0 * RS + t4 * 2);
            ah[mb][1] = *(const uint32_t*)(sAh + (r0 + 8) * RS + t4 * 2);
            ah[mb][2] = *(const uint32_t*)(sAh + r0 * RS + 8 + t4 * 2);
            ah[mb][3] = *(const uint32_t*)(sAh + (r0 + 8) * RS + 8 + t4 * 2);
            al[mb][0] = *(const uint32_t*)(sAl + r0 * RS + t4 * 2);
            al[mb][1] = *(const uint32_t*)(sAl + (r0 + 8) * RS + t4 * 2);
            al[mb][2] = *(const uint32_t*)(sAl + r0 * RS + 8 + t4 * 2);
            al[mb][3] = *(const uint32_t*)(sAl + (r0 + 8) * RS + 8 + t4 * 2);
        }
#pragma unroll
        for (int nb = 0; nb < 8; nb++) {
            const int n0 = warp_n * 64 + nb * 8 + g;
            uint32_t bh[2], bl[2];
            bh[0] = *(const uint32_t*)(sBh + n0 * RS + t4 * 2);
            bh[1] = *(const uint32_t*)(sBh + n0 * RS + 8 + t4 * 2);
            bl[0] = *(const uint32_t*)(sBl + n0 * RS + t4 * 2);
            bl[1] = *(const uint32_t*)(sBl + n0 * RS + 8 + t4 * 2);
#pragma unroll
            for (int mb = 0; mb < 2; mb++) {
                mma_bf16(c[mb][nb], ah[mb], bh);
                mma_bf16(c[mb][nb], ah[mb], bl);
                mma_bf16(c[mb][nb], al[mb], bh);
            }
        }
    }

    float* zd = zbase + ((size_t)dir * 129024 + m0) * 128;
#pragma unroll
    for (int mb = 0; mb < 2; mb++) {
        const int r0 = warp_m * 32 + mb * 16 + g;
#pragma unroll
        for (int nb = 0; nb < 8; nb++) {
            const int col = warp_n * 64 + nb * 8 + t4 * 2;
            zd[(size_t)r0 * 128 + col] = c[mb][nb][0] + bias[col];
            zd[(size_t)r0 * 128 + col + 1] = c[mb][nb][1] + bias[col + 1];
            zd[(size_t)(r0 + 8) * 128 + col] = c[mb][nb][2] + bias[col];
            zd[(size_t)(r0 + 8) * 128 + col + 1] = c[mb][nb][3] + bias[col + 1];
        }
    }
}

// ---------------------------------------------------------------------------
// Scalar x-conv over ALL timesteps (L1, L3).
// ---------------------------------------------------------------------------
template <int CIN, int F, int H, int W, int TH, int SUBS>
__global__ __launch_bounds__(SUBS * 4 * F) void xconv_all(
    const float* __restrict__ xin,
    const float* __restrict__ wxf, const float* __restrict__ wxb,
    const float* __restrict__ bf, const float* __restrict__ bb,
    float* __restrict__ zbase) {
    constexpr int OC = 4 * F;
    constexpr int NT = SUBS * OC;
    constexpr int THS = TH / SUBS;
    constexpr int TW = 14, TW2 = 16;
    constexpr int CSTRIDE = (TH + 2) * TW2 + 4;
    constexpr int TILES_W = W / TW;

    __shared__ __align__(16) float smem[CIN * CSTRIDE];

    const int dir = blockIdx.z;
    const int bt = blockIdx.y;
    const int tile = blockIdx.x;
    const int ty0 = (tile / TILES_W) * TH;
    const int tx0 = (tile % TILES_W) * TW;

    const float* wx = dir ? wxb : wxf;
    const float* bi = dir ? bb : bf;
    const float* xb = xin + (size_t)bt * H * W * CIN;
    const int b = bt / TT, t = bt % TT;

    const int tid = threadIdx.x;

    constexpr int TOTAL = (TH + 2) * TW2 * CIN;
    for (int idx = tid; idx < TOTAL; idx += NT) {
        int c = idx % CIN;
        int p = idx / CIN;
        int yy = p / TW2, xx = p % TW2;
        int gy = ty0 + yy - 1, gx = tx0 + xx - 1;
        float v = 0.f;
        if (gy >= 0 && gy < H && gx >= 0 && gx < W)
            v = xb[((size_t)gy * W + gx) * CIN + c];
        smem[c * CSTRIDE + yy * TW2 + xx] = v;
    }
    __syncthreads();

    const int oc = tid % OC;
    const int sub = tid / OC;

    float acc[THS][TW];
    {
        const float bv = bi[oc];
#pragma unroll
        for (int y = 0; y < THS; y++)
#pragma unroll
            for (int p = 0; p < TW; p++) acc[y][p] = bv;
    }

#pragma unroll 2
    for (int c = 0; c < CIN; c++) {
        const float* sc = smem + c * CSTRIDE + sub * THS * TW2;
        float w[9];
#pragma unroll
        for (int k = 0; k < 9; k++) w[k] = wx[((size_t)k * CIN + c) * OC + oc];
#pragma unroll
        for (int iy = 0; iy < THS + 2; iy++) {
            float seg[TW2];
#pragma unroll
            for (int q = 0; q < TW2 / 4; q++) {
                const float4 v =
                    *reinterpret_cast<const float4*>(sc + iy * TW2 + 4 * q);
                seg[4 * q] = v.x; seg[4 * q + 1] = v.y;
                seg[4 * q + 2] = v.z; seg[4 * q + 3] = v.w;
            }
#pragma unroll
            for (int dy = 0; dy < 3; dy++) {
                const int ry = iy - dy;
                if (ry >= 0 && ry < THS) {
#pragma unroll
                    for (int dx = 0; dx < 3; dx++) {
                        const float ww = w[dy * 3 + dx];
#pragma unroll
                        for (int p = 0; p < TW; p++)
                            acc[ry][p] = fmaf(ww, seg[p + dx], acc[ry][p]);
                    }
                }
            }
        }
    }

    float* zb = zbase + (((size_t)(dir * BB + b) * TT + t) * H * W +
                         (size_t)ty0 * W + tx0) * OC;
#pragma unroll
    for (int y = 0; y < THS; y++)
#pragma unroll
        for (int p = 0; p < TW; p++)
            zb[((size_t)(sub * THS + y) * W + p) * OC + oc] = acc[y][p];
}

// ---------------------------------------------------------------------------
// Layer 3 persistent kernel.
// ---------------------------------------------------------------------------
__global__ __launch_bounds__(288) void lstm3_persistent(
    const float* __restrict__ zbase,
    const float* __restrict__ whf, const float* __restrict__ whb,
    float* __restrict__ out) {
    constexpr int F = 12, OC = 48, H = 12, W = 14, HW = H * W;
    constexpr int TW2 = 16, CSTR = (H + 2) * TW2 + 4;

    __shared__ __align__(16) float sh[F * CSTR];
    __shared__ __align__(16) float sz[HW * OC];

    const int dirb = blockIdx.x;
    const int dir = dirb / BB;
    const int b = dirb % BB;
    const float* wh = dir ? whb : whf;
    const int tid = threadIdx.x;

    for (int i = tid; i < F * CSTR; i += 288) sh[i] = 0.f;

    const int f = tid % F;
    const int pidx = tid / F;
    float creg[7];
#pragma unroll
    for (int k = 0; k < 7; k++) creg[k] = 0.f;

    const int oc = tid % OC;
    const int sub = tid / OC;

    for (int j = 0; j < TT; j++) {
        const int t = dir ? (TT - 1 - j) : j;
        __syncthreads();

        const float* zb = zbase + ((size_t)dirb * TT + t) * HW * OC;
        float acc[2][14];
#pragma unroll
        for (int y = 0; y < 2; y++)
#pragma unroll
            for (int p = 0; p < 14; p++)
                acc[y][p] = zb[((sub * 2 + y) * W + p) * OC + oc];

#pragma unroll
        for (int c = 0; c < F; c++) {
            const float* sc = sh + c * CSTR + sub * 2 * TW2;
            float w[9];
#pragma unroll
            for (int k = 0; k < 9; k++) w[k] = wh[((size_t)k * F + c) * OC + oc];
#pragma unroll
            for (int iy = 0; iy < 4; iy++) {
                float seg[16];
#pragma unroll
                for (int q = 0; q < 4; q++) {
                    const float4 v =
                        *reinterpret_cast<const float4*>(sc + iy * TW2 + 4 * q);
                    seg[4 * q] = v.x; seg[4 * q + 1] = v.y;
                    seg[4 * q + 2] = v.z; seg[4 * q + 3] = v.w;
                }
#pragma unroll
                for (int dy = 0; dy < 3; dy++) {
                    const int ry = iy - dy;
                    if (ry >= 0 && ry < 2) {
#pragma unroll
                        for (int dx = 0; dx < 3; dx++) {
                            const float ww = w[dy * 3 + dx];
#pragma unroll
                            for (int p = 0; p < 14; p++)
                                acc[ry][p] = fmaf(ww, seg[p + dx], acc[ry][p]);
                        }
                    }
                }
            }
        }

        __syncthreads();
#pragma unroll
        for (int y = 0; y < 2; y++)
#pragma unroll
            for (int p = 0; p < 14; p++)
                sz[((sub * 2 + y) * W + p) * OC + oc] = acc[y][p];
        __syncthreads();

        float* sq = out + ((size_t)(b * TT + t) * HW) * 24 + dir * F;
#pragma unroll
        for (int k = 0; k < 7; k++) {
            const int pos = pidx + 24 * k;
            const float zi = sz[pos * OC + f];
            const float zf = sz[pos * OC + F + f];
            const float zg = sz[pos * OC + 2 * F + f];
            const float zo = sz[pos * OC + 3 * F + f];
            const float ig = fmaxf(zi, 0.f);
            const float fg = fmaxf(zf, 0.f);
            const float gg = tanhf(zg);
            const float og = fmaxf(zo, 0.f);
            const float cn = fg * creg[k] + ig * gg;
            const float hn = og * tanhf(cn);
            creg[k] = cn;
            sq[pos * 24 + f] = hn;
            const int y = pos / W, x = pos % W;
            sh[f * CSTR + (y + 1) * TW2 + (x + 1)] = hn;
        }
    }

    __syncthreads();
    const size_t SEQ3 = (size_t)BB * TT * HW * 24;
    const size_t ST3 = (size_t)BB * HW * F;
    float* oh = out + SEQ3 + (size_t)(2 * dir) * ST3;
    float* ocst = out + SEQ3 + (size_t)(2 * dir + 1) * ST3;
#pragma unroll
    for (int k = 0; k < 7; k++) {
        const int pos = pidx + 24 * k;
        const int y = pos / W, x = pos % W;
        oh[((size_t)b * HW + pos) * F + f] = sh[f * CSTR + (y + 1) * TW2 + (x + 1)];
        ocst[((size_t)b * HW + pos) * F + f] = creg[k];
    }
}

// ---------------------------------------------------------------------------
// BN (eps=1e-3) then 2x2 max pool.
// ---------------------------------------------------------------------------
__global__ void bnpool_kernel(const float* __restrict__ in,
                              float* __restrict__ out,
                              const float* __restrict__ gg,
                              const float* __restrict__ bb,
                              const float* __restrict__ mm,
                              const float* __restrict__ vv, int H, int W,
                              int C) {
    const int HO = H / 2, WO = W / 2;
    const size_t total = (size_t)BB * TT * HO * WO * C;
    size_t i = (size_t)blockIdx.x * blockDim.x + threadIdx.x;
    if (i >= total) return;
    const int c = i % C;
    size_t r = i / C;
    const int x = r % WO;
    r /= WO;
    const int y = r % HO;
    r /= HO;
    const int t = r % TT;
    const int b = r / TT;

    const float scale = gg[c] * rsqrtf(vv[c] + 1e-3f);
    const float shift = bb[c] - mm[c] * scale;

    const float* base = in + ((size_t)(b * TT + t)) * H * W * C;
    float mx = -3.402823e38f;
#pragma unroll
    for (int dy = 0; dy < 2; dy++)
#pragma unroll
        for (int dx = 0; dx < 2; dx++) {
            float v =
                base[((size_t)(2 * y + dy) * W + (2 * x + dx)) * C + c] * scale +
                shift;
            mx = fmaxf(mx, v);
        }
    out[i] = mx;
}

// ---------------------------------------------------------------------------
// Host side
// ---------------------------------------------------------------------------
static float* sym_addr(const void* symbol) {
    void* p = nullptr;
    cudaGetSymbolAddress(&p, symbol);
    return (float*)p;
}
static __nv_bfloat16* sym_addr_bf(const void* symbol) {
    void* p = nullptr;
    cudaGetSymbolAddress(&p, symbol);
    return (__nv_bfloat16*)p;
}
static uint4* sym_addr_u4(const void* symbol) {
    void* p = nullptr;
    cudaGetSymbolAddress(&p, symbol);
    return (uint4*)p;
}

extern "C" void kernel_launch(void* const* d_in, const int* in_sizes, int n_in,
                              void* d_out, int out_size) {
    const float* x = (const float*)d_in[0];
    const float* w1f_x = (const float*)d_in[1];
    const float* w1f_h = (const float*)d_in[2];
    const float* b1f = (const float*)d_in[3];
    const float* w1b_x = (const float*)d_in[4];
    const float* w1b_h = (const float*)d_in[5];
    const float* b1b = (const float*)d_in[6];
    const float* w2f_x = (const float*)d_in[7];
    const float* w2f_h = (const float*)d_in[8];
    const float* b2f = (const float*)d_in[9];
    const float* w2b_x = (const float*)d_in[10];
    const float* w2b_h = (const float*)d_in[11];
    const float* b2b = (const float*)d_in[12];
    const float* w3f_x = (const float*)d_in[13];
    const float* w3f_h = (const float*)d_in[14];
    const float* b3f = (const float*)d_in[15];
    const float* w3b_x = (const float*)d_in[16];
    const float* w3b_h = (const float*)d_in[17];
    const float* b3b = (const float*)d_in[18];
    const float* bn1_g = (const float*)d_in[19];
    const float* bn1_b = (const float*)d_in[20];
    const float* bn1_m = (const float*)d_in[21];
    const float* bn1_v = (const float*)d_in[22];
    const float* bn2_g = (const float*)d_in[23];
    const float* bn2_b = (const float*)d_in[24];
    const float* bn2_m = (const float*)d_in[25];
    const float* bn2_v = (const float*)d_in[26];

    float* seq1 = sym_addr(g_seq1);
    float* p1 = sym_addr(g_p1);
    float* seq2 = sym_addr(g_seq2);
    float* p2 = sym_addr(g_p2);
    float* zb = sym_addr(g_zbase);
    float* cp = sym_addr(g_c);
    __nv_bfloat16* Bhi = sym_addr_bf(g_Bhi);
    __nv_bfloat16* Blo = sym_addr_bf(g_Blo);
    __nv_bfloat16* hhi[2] = {sym_addr_bf(g_hhiA), sym_addr_bf(g_hhiB)};
    __nv_bfloat16* hlo[2] = {sym_addr_bf(g_hloA), sym_addr_bf(g_hloB)};
    uint4* W1f4 = sym_addr_u4(g_W1f4);
    uint4* W2f4 = sym_addr_u4(g_W2f4);

    float* out = (float*)d_out;

    // ---- prep: weight packing/splitting ----
    bsplit2_kernel<<<(2 * 128 * 576 + 255) / 256, 256>>>(w2f_x, w2b_x, Bhi, Blo);
    wfrag_kernel<<<(2 * 2 * 9 * 2 * 16 * 32 + 255) / 256, 256>>>(
        w1f_h, w1b_h, w2f_h, w2b_h);

    // ================= Layer 1: 48x56, Cin=6, F=32 ========================
    {
        xconv_all<6, 32, 48, 56, 4, 2><<<dim3(48, BB * TT, 2), 256>>>(
            x, w1f_x, w1b_x, b1f, b1b, zb);
        const size_t hbytes = (size_t)2 * BB * 2688 * 32 * sizeof(__nv_bfloat16);
        cudaMemsetAsync(hhi[0], 0, hbytes);
        cudaMemsetAsync(hlo[0], 0, hbytes);
        cudaMemsetAsync(cp, 0, (size_t)2 * BB * 2688 * 32 * sizeof(float));
        for (int j = 0; j < TT; j++) {
            hconv_mma<48, 56, 1, 64, 6, 2><<<dim3(48, BB, 2), 256>>>(
                zb, hhi[j & 1], hlo[j & 1], hhi[(j + 1) & 1], hlo[(j + 1) & 1],
                cp, W1f4, seq1, 64, j);
        }
        const size_t ptot = (size_t)BB * TT * 24 * 28 * 64;
        bnpool_kernel<<<(unsigned)((ptot + 255) / 256), 256>>>(
            seq1, p1, bn1_g, bn1_b, bn1_m, bn1_v, 48, 56, 64);
    }

    // ================= Layer 2: 24x28, Cin=64, F=32 =======================
    {
        gemm_xconv2<<<dim3(1008, 2), 256>>>(p1, Bhi, Blo, b2f, b2b, zb);
        const size_t hbytes = (size_t)2 * BB * 672 * 32 * sizeof(__nv_bfloat16);
        cudaMemsetAsync(hhi[0], 0, hbytes);
        cudaMemsetAsync(hlo[0], 0, hbytes);
        cudaMemsetAsync(cp, 0, (size_t)2 * BB * 672 * 32 * sizeof(float));
        for (int j = 0; j < TT; j++) {
            hconv_mma<24, 28, 1, 32, 5, 1><<<dim3(24, BB, 2), 256>>>(
                zb, hhi[j & 1], hlo[j & 1], hhi[(j + 1) & 1], hlo[(j + 1) & 1],
                cp, W2f4, seq2, 64, j);
        }
        const size_t ptot = (size_t)BB * TT * 12 * 14 * 64;
        bnpool_kernel<<<(unsigned)((ptot + 255) / 256), 256>>>(
            seq2, p2, bn2_g, bn2_b, bn2_m, bn2_v, 24, 28, 64);
    }

    // ================= Layer 3: 12x14, Cin=64, F=12 (persistent) ===========
    {
        xconv_all<64, 12, 12, 14, 4, 4><<<dim3(3, BB * TT, 2), 192>>>(
            p2, w3f_x, w3b_x, b3f, b3b, zb);
        lstm3_persistent<<<16, 288>>>(zb, w3f_h, w3b_h, out);
    }
}